// round 1
// baseline (speedup 1.0000x reference)
#include <cuda_runtime.h>

#define S_LEN 2048
#define B_SZ  4
#define H_NUM 8
#define DKH   128
#define DM    1024

// Scratch (device globals — no allocations allowed)
__device__ float g_Q[(size_t)B_SZ * H_NUM * S_LEN * DKH];  // [B,H,S,dk]
__device__ float g_K[(size_t)B_SZ * H_NUM * S_LEN * DKH];
__device__ float g_V[(size_t)B_SZ * H_NUM * S_LEN * DKH];
__device__ float g_O[(size_t)B_SZ * S_LEN * DM];           // [B,S,D]

// ---------------------------------------------------------------------------
// GEMM: Y = X @ W + b, M=8192, N=1024, K=1024. Output in [B,H,S,dk] layout.
// 128x128 tile, BK=16, 256 threads, 8x8 per thread.
// ---------------------------------------------------------------------------
__global__ __launch_bounds__(256, 2)
void gemm_qkv(const float* __restrict__ X, const float* __restrict__ W,
              const float* __restrict__ bias, float* __restrict__ out)
{
    __shared__ float As[16][128];   // A transposed: As[k][m]
    __shared__ float Bs[16][128];   // Bs[k][n]

    const int n0 = blockIdx.x * 128;        // h = blockIdx.x (BN == dk == 128)
    const int m0 = blockIdx.y * 128;
    const int tid = threadIdx.x;
    const int tx = tid & 15;
    const int ty = tid >> 4;

    float acc[8][8];
#pragma unroll
    for (int i = 0; i < 8; ++i)
#pragma unroll
        for (int j = 0; j < 8; ++j) acc[i][j] = 0.0f;

    for (int k0 = 0; k0 < 1024; k0 += 16) {
#pragma unroll
        for (int t = 0; t < 2; ++t) {
            int f   = tid + t * 256;
            int row = f >> 2;             // 0..127
            int c4  = (f & 3) * 4;        // 0,4,8,12
            float4 v = *reinterpret_cast<const float4*>(
                X + (size_t)(m0 + row) * 1024 + k0 + c4);
            As[c4 + 0][row] = v.x;
            As[c4 + 1][row] = v.y;
            As[c4 + 2][row] = v.z;
            As[c4 + 3][row] = v.w;
        }
#pragma unroll
        for (int t = 0; t < 2; ++t) {
            int f   = tid + t * 256;
            int row = f >> 5;             // 0..15
            int c   = (f & 31) * 4;       // 0..124
            *reinterpret_cast<float4*>(&Bs[row][c]) =
                *reinterpret_cast<const float4*>(
                    W + (size_t)(k0 + row) * 1024 + n0 + c);
        }
        __syncthreads();

#pragma unroll
        for (int kk = 0; kk < 16; ++kk) {
            float a[8], b[8];
            *reinterpret_cast<float4*>(a)     = *reinterpret_cast<float4*>(&As[kk][ty * 8]);
            *reinterpret_cast<float4*>(a + 4) = *reinterpret_cast<float4*>(&As[kk][ty * 8 + 4]);
            *reinterpret_cast<float4*>(b)     = *reinterpret_cast<float4*>(&Bs[kk][tx * 8]);
            *reinterpret_cast<float4*>(b + 4) = *reinterpret_cast<float4*>(&Bs[kk][tx * 8 + 4]);
#pragma unroll
            for (int i = 0; i < 8; ++i)
#pragma unroll
                for (int j = 0; j < 8; ++j)
                    acc[i][j] += a[i] * b[j];
        }
        __syncthreads();
    }

    // Epilogue: bias + head-split store. h = blockIdx.x, d = tx*8+j (contiguous).
    const int h = blockIdx.x;
    float4 bv0 = *reinterpret_cast<const float4*>(bias + n0 + tx * 8);
    float4 bv1 = *reinterpret_cast<const float4*>(bias + n0 + tx * 8 + 4);
#pragma unroll
    for (int i = 0; i < 8; ++i) {
        int m = m0 + ty * 8 + i;
        int b = m >> 11;
        int s = m & 2047;
        float* op = out + ((((size_t)b * H_NUM + h) * S_LEN + s) * DKH) + tx * 8;
        float4 r0, r1;
        r0.x = acc[i][0] + bv0.x; r0.y = acc[i][1] + bv0.y;
        r0.z = acc[i][2] + bv0.z; r0.w = acc[i][3] + bv0.w;
        r1.x = acc[i][4] + bv1.x; r1.y = acc[i][5] + bv1.y;
        r1.z = acc[i][6] + bv1.z; r1.w = acc[i][7] + bv1.w;
        *reinterpret_cast<float4*>(op)     = r0;
        *reinterpret_cast<float4*>(op + 4) = r1;
    }
}

// ---------------------------------------------------------------------------
// Flash attention, causal. BQ=BKV=64, dk=128, 256 threads (16x16).
// Row stats (m, l) replicated across the 16-lane row-owner group (shuffles).
// ---------------------------------------------------------------------------
__global__ __launch_bounds__(256, 2)
void attn_fwd(const float* __restrict__ Q, const float* __restrict__ K,
              const float* __restrict__ V, float* __restrict__ O)
{
    extern __shared__ float sm[];
    float* Qs = sm;               // [128][64] (d-major, transposed)
    float* Ks = Qs + 128 * 64;    // [128][64]
    float* Vs = Ks + 128 * 64;    // [64][128]
    float* Ps = Vs + 64 * 128;    // [64][65] (padded)

    const int qt  = (int)gridDim.x - 1 - (int)blockIdx.x;  // heavy tiles first
    const int bh  = blockIdx.y;
    const int tid = threadIdx.x;
    const int tx  = tid & 15;
    const int ty  = tid >> 4;

    const float* Qg = Q + ((size_t)bh * S_LEN + (size_t)qt * 64) * DKH;
    const float* Kg = K + (size_t)bh * S_LEN * DKH;
    const float* Vg = V + (size_t)bh * S_LEN * DKH;

    // Load Q tile transposed: Qs[d][r]
#pragma unroll
    for (int t = 0; t < 8; ++t) {
        int f = tid + t * 256;
        int r = f >> 5;
        int d = (f & 31) * 4;
        float4 v = *reinterpret_cast<const float4*>(Qg + (size_t)r * DKH + d);
        Qs[(d + 0) * 64 + r] = v.x;
        Qs[(d + 1) * 64 + r] = v.y;
        Qs[(d + 2) * 64 + r] = v.z;
        Qs[(d + 3) * 64 + r] = v.w;
    }

    float m[4], l[4], acc[4][8];
#pragma unroll
    for (int i = 0; i < 4; ++i) {
        m[i] = -1e30f;
        l[i] = 0.0f;
#pragma unroll
        for (int j = 0; j < 8; ++j) acc[i][j] = 0.0f;
    }

    const float sc = 0.08838834764831843f;  // 1/sqrt(128)

    for (int kt = 0; kt <= qt; ++kt) {
        __syncthreads();  // previous iter done with Ks/Vs/Ps (also covers Q load)

        const float* Kt = Kg + (size_t)kt * 64 * DKH;
        const float* Vt = Vg + (size_t)kt * 64 * DKH;
#pragma unroll
        for (int t = 0; t < 8; ++t) {
            int f = tid + t * 256;
            int r = f >> 5;
            int d = (f & 31) * 4;
            float4 v = *reinterpret_cast<const float4*>(Kt + (size_t)r * DKH + d);
            Ks[(d + 0) * 64 + r] = v.x;
            Ks[(d + 1) * 64 + r] = v.y;
            Ks[(d + 2) * 64 + r] = v.z;
            Ks[(d + 3) * 64 + r] = v.w;
        }
#pragma unroll
        for (int t = 0; t < 8; ++t) {
            int f = tid + t * 256;
            *reinterpret_cast<float4*>(Vs + f * 4) =
                *reinterpret_cast<const float4*>(Vt + f * 4);
        }
        __syncthreads();

        // S = Q @ K^T  (4x4 per thread; rows ty*4+i, cols tx*4+j)
        float s[4][4];
#pragma unroll
        for (int i = 0; i < 4; ++i)
#pragma unroll
            for (int j = 0; j < 4; ++j) s[i][j] = 0.0f;

#pragma unroll 4
        for (int d = 0; d < 128; ++d) {
            float4 q4 = reinterpret_cast<const float4*>(Qs + d * 64)[ty];
            float4 k4 = reinterpret_cast<const float4*>(Ks + d * 64)[tx];
            const float* qa = reinterpret_cast<const float*>(&q4);
            const float* ka = reinterpret_cast<const float*>(&k4);
#pragma unroll
            for (int i = 0; i < 4; ++i)
#pragma unroll
                for (int j = 0; j < 4; ++j)
                    s[i][j] += qa[i] * ka[j];
        }

#pragma unroll
        for (int i = 0; i < 4; ++i)
#pragma unroll
            for (int j = 0; j < 4; ++j) s[i][j] *= sc;

        if (kt == qt) {  // diagonal tile: causal mask
#pragma unroll
            for (int i = 0; i < 4; ++i)
#pragma unroll
                for (int j = 0; j < 4; ++j)
                    if (tx * 4 + j > ty * 4 + i) s[i][j] = -1e9f;
        }

        // Row max over 64 cols: local max + butterfly over the 16-lane group
        float rm[4];
#pragma unroll
        for (int i = 0; i < 4; ++i)
            rm[i] = fmaxf(fmaxf(s[i][0], s[i][1]), fmaxf(s[i][2], s[i][3]));
#pragma unroll
        for (int off = 1; off < 16; off <<= 1)
#pragma unroll
            for (int i = 0; i < 4; ++i)
                rm[i] = fmaxf(rm[i], __shfl_xor_sync(0xffffffffu, rm[i], off));

        float corr[4];
#pragma unroll
        for (int i = 0; i < 4; ++i) {
            float mn = fmaxf(m[i], rm[i]);
            corr[i]  = __expf(m[i] - mn);
            m[i]     = mn;
        }

        float rs[4];
#pragma unroll
        for (int i = 0; i < 4; ++i) {
            rs[i] = 0.0f;
#pragma unroll
            for (int j = 0; j < 4; ++j) {
                s[i][j] = __expf(s[i][j] - m[i]);
                rs[i] += s[i][j];
            }
        }
#pragma unroll
        for (int off = 1; off < 16; off <<= 1)
#pragma unroll
            for (int i = 0; i < 4; ++i)
                rs[i] += __shfl_xor_sync(0xffffffffu, rs[i], off);

#pragma unroll
        for (int i = 0; i < 4; ++i) {
            l[i] = l[i] * corr[i] + rs[i];
#pragma unroll
            for (int j = 0; j < 8; ++j) acc[i][j] *= corr[i];
        }

        // P -> smem for the PV GEMM (cols redistributed across tx)
#pragma unroll
        for (int i = 0; i < 4; ++i)
#pragma unroll
            for (int j = 0; j < 4; ++j)
                Ps[(ty * 4 + i) * 65 + tx * 4 + j] = s[i][j];
        __syncthreads();

        // O += P @ V  (cols tx*8..tx*8+7)
#pragma unroll 2
        for (int k = 0; k < 64; ++k) {
            float4 v0 = reinterpret_cast<const float4*>(Vs + k * 128)[tx * 2];
            float4 v1 = reinterpret_cast<const float4*>(Vs + k * 128)[tx * 2 + 1];
#pragma unroll
            for (int i = 0; i < 4; ++i) {
                float pv = Ps[(ty * 4 + i) * 65 + k];
                acc[i][0] += pv * v0.x; acc[i][1] += pv * v0.y;
                acc[i][2] += pv * v0.z; acc[i][3] += pv * v0.w;
                acc[i][4] += pv * v1.x; acc[i][5] += pv * v1.y;
                acc[i][6] += pv * v1.z; acc[i][7] += pv * v1.w;
            }
        }
    }

    // Epilogue: normalize and write to [B,S,D]
    const int b = bh >> 3;
    const int h = bh & 7;
#pragma unroll
    for (int i = 0; i < 4; ++i) {
        float inv = 1.0f / l[i];
        int qi = qt * 64 + ty * 4 + i;
        float* op = O + ((size_t)b * S_LEN + qi) * DM + h * DKH + tx * 8;
        float4 r0, r1;
        r0.x = acc[i][0] * inv; r0.y = acc[i][1] * inv;
        r0.z = acc[i][2] * inv; r0.w = acc[i][3] * inv;
        r1.x = acc[i][4] * inv; r1.y = acc[i][5] * inv;
        r1.z = acc[i][6] * inv; r1.w = acc[i][7] * inv;
        *reinterpret_cast<float4*>(op)     = r0;
        *reinterpret_cast<float4*>(op + 4) = r1;
    }
}

// ---------------------------------------------------------------------------
// Residual + LayerNorm: one block per row, 256 threads, float4 per thread.
// ---------------------------------------------------------------------------
__global__ __launch_bounds__(256)
void ln_kernel(const float* __restrict__ Oin, const float* __restrict__ X,
               const float* __restrict__ gamma, const float* __restrict__ beta,
               float* __restrict__ out)
{
    const int r = blockIdx.x;
    const int t = threadIdx.x;

    float4 o = reinterpret_cast<const float4*>(Oin + (size_t)r * DM)[t];
    float4 x = reinterpret_cast<const float4*>(X + (size_t)r * DM)[t];
    float v0 = o.x + x.x, v1 = o.y + x.y, v2 = o.z + x.z, v3 = o.w + x.w;

    float s1 = v0 + v1 + v2 + v3;
    float s2 = v0 * v0 + v1 * v1 + v2 * v2 + v3 * v3;
#pragma unroll
    for (int off = 16; off > 0; off >>= 1) {
        s1 += __shfl_xor_sync(0xffffffffu, s1, off);
        s2 += __shfl_xor_sync(0xffffffffu, s2, off);
    }

    __shared__ float rs1[8], rs2[8], stats[2];
    int warp = t >> 5, lane = t & 31;
    if (lane == 0) { rs1[warp] = s1; rs2[warp] = s2; }
    __syncthreads();
    if (t == 0) {
        float a = 0.0f, b2 = 0.0f;
#pragma unroll
        for (int w = 0; w < 8; ++w) { a += rs1[w]; b2 += rs2[w]; }
        float mean = a * (1.0f / 1024.0f);
        float var  = b2 * (1.0f / 1024.0f) - mean * mean;
        stats[0] = mean;
        stats[1] = rsqrtf(var + 1e-6f);
    }
    __syncthreads();
    float mean = stats[0], rstd = stats[1];

    float4 g  = reinterpret_cast<const float4*>(gamma)[t];
    float4 bb = reinterpret_cast<const float4*>(beta)[t];
    float4 y;
    y.x = (v0 - mean) * rstd * g.x + bb.x;
    y.y = (v1 - mean) * rstd * g.y + bb.y;
    y.z = (v2 - mean) * rstd * g.z + bb.z;
    y.w = (v3 - mean) * rstd * g.w + bb.w;
    reinterpret_cast<float4*>(out + (size_t)r * DM)[t] = y;
}

// ---------------------------------------------------------------------------
// Launcher
// ---------------------------------------------------------------------------
extern "C" void kernel_launch(void* const* d_in, const int* in_sizes, int n_in,
                              void* d_out, int out_size)
{
    const float* q     = (const float*)d_in[0];
    const float* k     = (const float*)d_in[1];
    const float* v     = (const float*)d_in[2];
    const float* Wq    = (const float*)d_in[3];
    const float* bq    = (const float*)d_in[4];
    const float* Wk    = (const float*)d_in[5];
    const float* bk    = (const float*)d_in[6];
    const float* Wv    = (const float*)d_in[7];
    const float* bv    = (const float*)d_in[8];
    const float* gamma = (const float*)d_in[9];
    const float* beta  = (const float*)d_in[10];
    float* out = (float*)d_out;

    float *Qp, *Kp, *Vp, *Op;
    cudaGetSymbolAddress((void**)&Qp, g_Q);
    cudaGetSymbolAddress((void**)&Kp, g_K);
    cudaGetSymbolAddress((void**)&Vp, g_V);
    cudaGetSymbolAddress((void**)&Op, g_O);

    const int ATTN_SMEM = (128 * 64 + 128 * 64 + 64 * 128 + 64 * 65) * 4;  // 114944 B
    cudaFuncSetAttribute(attn_fwd, cudaFuncAttributeMaxDynamicSharedMemorySize,
                         ATTN_SMEM);

    dim3 ggrid(8, 64);
    gemm_qkv<<<ggrid, 256>>>(q, Wq, bq, Qp);
    gemm_qkv<<<ggrid, 256>>>(k, Wk, bk, Kp);
    gemm_qkv<<<ggrid, 256>>>(v, Wv, bv, Vp);

    attn_fwd<<<dim3(32, 32), 256, ATTN_SMEM>>>(Qp, Kp, Vp, Op);

    ln_kernel<<<8192, 256>>>(Op, q, gamma, beta, out);
}

// round 3
// speedup vs baseline: 3.9948x; 3.9948x over previous
#include <cuda_runtime.h>
#include <cstdint>

#define S_LEN 2048
#define B_SZ  4
#define H_NUM 8
#define DKH   128
#define DM    1024

// Scratch (device globals — no allocations allowed)
__device__ float g_Q[(size_t)B_SZ * H_NUM * S_LEN * DKH];  // [B,H,S,dk]
__device__ float g_K[(size_t)B_SZ * H_NUM * S_LEN * DKH];
__device__ float g_V[(size_t)B_SZ * H_NUM * S_LEN * DKH];
__device__ float g_O[(size_t)B_SZ * S_LEN * DM];           // [B,S,D]
__device__ float g_WqT[DM * DM];                           // W transposed: [n][k]
__device__ float g_WkT[DM * DM];
__device__ float g_WvT[DM * DM];

// ---------------------------------------------------------------------------
// helpers
// ---------------------------------------------------------------------------
__device__ __forceinline__ float tf32r(float x) {   // round-to-nearest tf32
    uint32_t u;
    asm("cvt.rna.tf32.f32 %0, %1;" : "=r"(u) : "f"(x));
    return __uint_as_float(u);
}
__device__ __forceinline__ float4 tf4(float4 v) {
    return make_float4(tf32r(v.x), tf32r(v.y), tf32r(v.z), tf32r(v.w));
}
__device__ __forceinline__ uint32_t fbits(float x) { return __float_as_uint(x); }

// D += A*B, m16n8k8 tf32 (warp-level fallback HMMA; works on target sm_103)
__device__ __forceinline__ void mma8(float* d, const uint32_t* a, const uint32_t* b) {
    asm volatile(
        "mma.sync.aligned.m16n8k8.row.col.f32.tf32.tf32.f32 "
        "{%0,%1,%2,%3},{%4,%5,%6,%7},{%8,%9},{%0,%1,%2,%3};"
        : "+f"(d[0]), "+f"(d[1]), "+f"(d[2]), "+f"(d[3])
        : "r"(a[0]), "r"(a[1]), "r"(a[2]), "r"(a[3]), "r"(b[0]), "r"(b[1]));
}

// ---------------------------------------------------------------------------
// Tiled 1024x1024 transpose: out[n][k] = in[k][n]
// ---------------------------------------------------------------------------
__global__ __launch_bounds__(256)
void transpose1024(const float* __restrict__ in, float* __restrict__ out)
{
    __shared__ float t[32][33];
    int x  = blockIdx.x * 32 + threadIdx.x;
    int y0 = blockIdx.y * 32;
#pragma unroll
    for (int j = threadIdx.y; j < 32; j += 8)
        t[j][threadIdx.x] = in[(size_t)(y0 + j) * DM + x];
    __syncthreads();
    int x2 = blockIdx.y * 32 + threadIdx.x;
#pragma unroll
    for (int j = threadIdx.y; j < 32; j += 8)
        out[(size_t)(blockIdx.x * 32 + j) * DM + x2] = t[threadIdx.x][j];
}

// ---------------------------------------------------------------------------
// tf32 mma.sync GEMM: Y = X @ W + b. M=8192 N=1024 K=1024.
// A = X[m][k], B = Wt[n][k] (both K-major). CTA 128x128, BK=32, 8 warps.
// smem stride 36 floats -> fragment loads conflict-free (bank = laneid).
// Output fused into [B,H,S,dk] layout with bias.
// ---------------------------------------------------------------------------
#define GST 36                       // smem row stride (floats)
#define GSTAGE (2 * 128 * GST)       // floats per stage (A+B)
#define GEMM_SMEM (2 * GSTAGE * 4)   // 73728 bytes

__global__ __launch_bounds__(256)
void gemm_mma(const float* __restrict__ X, const float* __restrict__ Wt,
              const float* __restrict__ bias, float* __restrict__ out)
{
    extern __shared__ float sg[];
    const int tid  = threadIdx.x;
    const int wid  = tid >> 5, lane = tid & 31;
    const int grp  = lane >> 2, kq = lane & 3;
    const int wm   = (wid >> 2) * 64, wn = (wid & 3) * 32;
    const int n0   = blockIdx.x * 128;   // h = blockIdx.x
    const int m0   = blockIdx.y * 128;

    float acc[4][4][4];
#pragma unroll
    for (int mt = 0; mt < 4; ++mt)
#pragma unroll
        for (int nt = 0; nt < 4; ++nt)
#pragma unroll
            for (int e = 0; e < 4; ++e) acc[mt][nt][e] = 0.0f;

    // slot decomposition for tile copies (128 rows x 32 cols, 4 f4/thread)
    const int sr[4] = { (tid + 0) >> 3, (tid + 256) >> 3, (tid + 512) >> 3, (tid + 768) >> 3 };
    const int sc    = (tid & 7) * 4;

    // stage 0 direct
#pragma unroll
    for (int j = 0; j < 4; ++j) {
        float4 va = *reinterpret_cast<const float4*>(X  + (size_t)(m0 + sr[j]) * 1024 + sc);
        float4 vb = *reinterpret_cast<const float4*>(Wt + (size_t)(n0 + sr[j]) * 1024 + sc);
        *reinterpret_cast<float4*>(sg + sr[j] * GST + sc)              = tf4(va);
        *reinterpret_cast<float4*>(sg + 128 * GST + sr[j] * GST + sc)  = tf4(vb);
    }
    __syncthreads();

    float4 pa[4], pb[4];
    for (int i = 0; i < 32; ++i) {
        float* Ac = sg + (i & 1) * GSTAGE;
        float* Bc = Ac + 128 * GST;

        if (i < 31) {
            const int kn = (i + 1) * 32;
#pragma unroll
            for (int j = 0; j < 4; ++j) {
                pa[j] = *reinterpret_cast<const float4*>(X  + (size_t)(m0 + sr[j]) * 1024 + kn + sc);
                pb[j] = *reinterpret_cast<const float4*>(Wt + (size_t)(n0 + sr[j]) * 1024 + kn + sc);
            }
        }

        const float* Ab = Ac + (wm + grp) * GST + kq;
        const float* Bb = Bc + (wn + grp) * GST + kq;
#pragma unroll
        for (int ks = 0; ks < 4; ++ks) {
            uint32_t a[4][4], b[4][2];
#pragma unroll
            for (int mt = 0; mt < 4; ++mt) {
                const float* p = Ab + mt * (16 * GST) + ks * 8;
                a[mt][0] = fbits(p[0]);
                a[mt][1] = fbits(p[8 * GST]);
                a[mt][2] = fbits(p[4]);
                a[mt][3] = fbits(p[8 * GST + 4]);
            }
#pragma unroll
            for (int nt = 0; nt < 4; ++nt) {
                const float* p = Bb + nt * (8 * GST) + ks * 8;
                b[nt][0] = fbits(p[0]);
                b[nt][1] = fbits(p[4]);
            }
#pragma unroll
            for (int mt = 0; mt < 4; ++mt)
#pragma unroll
                for (int nt = 0; nt < 4; ++nt)
                    mma8(acc[mt][nt], a[mt], b[nt]);
        }

        if (i < 31) {
            float* An = sg + ((i + 1) & 1) * GSTAGE;
            float* Bn = An + 128 * GST;
#pragma unroll
            for (int j = 0; j < 4; ++j) {
                *reinterpret_cast<float4*>(An + sr[j] * GST + sc) = tf4(pa[j]);
                *reinterpret_cast<float4*>(Bn + sr[j] * GST + sc) = tf4(pb[j]);
            }
        }
        __syncthreads();
    }

    // epilogue: bias + head-split store ([B,H,S,dk]); float2 per C-frag half
    const int h = blockIdx.x;
#pragma unroll
    for (int mt = 0; mt < 4; ++mt) {
        int mA = m0 + wm + mt * 16 + grp;
#pragma unroll
        for (int half = 0; half < 2; ++half) {
            int m = mA + half * 8;
            int b = m >> 11, s = m & 2047;
            float* orow = out + (((size_t)b * H_NUM + h) * S_LEN + s) * DKH;
#pragma unroll
            for (int nt = 0; nt < 4; ++nt) {
                int nl = wn + nt * 8 + 2 * kq;
                float2 bv = *reinterpret_cast<const float2*>(bias + n0 + nl);
                float2 r;
                r.x = acc[mt][nt][half * 2 + 0] + bv.x;
                r.y = acc[mt][nt][half * 2 + 1] + bv.y;
                *reinterpret_cast<float2*>(orow + nl) = r;
            }
        }
    }
}

// ---------------------------------------------------------------------------
// Flash attention on tf32 mma.sync. BQ=64, BKV=64, dk=128, 4 warps.
// Q A-fragments live in registers for the whole kernel.
// Ks stride 132 / Vs stride 136 / Ps stride 68 -> all frag loads conflict-free
// (or 2-way worst case). P staging is warp-private (syncwarp only).
// ---------------------------------------------------------------------------
#define KST 132
#define VST 136
#define PST 68
#define ATT_KS   0
#define ATT_VS   (64 * KST)                    // 8448
#define ATT_PS   (ATT_VS + 64 * VST)           // 17152
#define ATT_FLOATS (ATT_PS + 4 * 16 * PST)     // 21504
#define ATT_SMEM  (ATT_FLOATS * 4)             // 86016 bytes

__global__ __launch_bounds__(128)
void attn_mma(const float* __restrict__ Q, const float* __restrict__ K,
              const float* __restrict__ V, float* __restrict__ O)
{
    extern __shared__ float sa[];
    float* Ks = sa + ATT_KS;
    float* Vs = sa + ATT_VS;
    float* Ps = sa + ATT_PS;

    const int qt  = (int)gridDim.x - 1 - (int)blockIdx.x;  // heavy tiles first
    const int bh  = blockIdx.y;
    const int tid = threadIdx.x;
    const int w   = tid >> 5, lane = tid & 31;
    const int grp = lane >> 2, kq = lane & 3;

    const float* Qg = Q + ((size_t)bh * S_LEN + (size_t)qt * 64) * DKH;
    const float* Kg = K + (size_t)bh * S_LEN * DKH;
    const float* Vg = V + (size_t)bh * S_LEN * DKH;

    // ---- stage Q into Ks area, pull A-fragments to registers ----
    {
#pragma unroll
        for (int j = 0; j < 16; ++j) {
            int s = tid + j * 128;
            int r = s >> 5, c4 = (s & 31) * 4;
            float4 v = tf4(*reinterpret_cast<const float4*>(Qg + (size_t)r * DKH + c4));
            *reinterpret_cast<float4*>(Ks + r * KST + c4) = v;
        }
        __syncthreads();
    }
    uint32_t qa[16][4];
    {
        const float* qb = Ks + (w * 16 + grp) * KST + kq;
#pragma unroll
        for (int ks = 0; ks < 16; ++ks) {
            qa[ks][0] = fbits(qb[ks * 8]);
            qa[ks][1] = fbits(qb[8 * KST + ks * 8]);
            qa[ks][2] = fbits(qb[ks * 8 + 4]);
            qa[ks][3] = fbits(qb[8 * KST + ks * 8 + 4]);
        }
    }

    float o[16][4];
#pragma unroll
    for (int nt = 0; nt < 16; ++nt)
#pragma unroll
        for (int e = 0; e < 4; ++e) o[nt][e] = 0.0f;
    float m0 = -1e30f, m1 = -1e30f, l0 = 0.0f, l1 = 0.0f;

    const float sc = 0.08838834764831843f;  // 1/sqrt(128)
    const int rowlo = w * 16 + grp;          // tile-local row of c0,c1
    const int rowhi = rowlo + 8;             // c2,c3

    for (int kt = 0; kt <= qt; ++kt) {
        __syncthreads();   // everyone done with previous Ks/Vs (and Q staging)

        const float* Kt = Kg + (size_t)kt * 64 * DKH;
        const float* Vt = Vg + (size_t)kt * 64 * DKH;
#pragma unroll
        for (int j = 0; j < 16; ++j) {
            int s = tid + j * 128;
            int r = s >> 5, c4 = (s & 31) * 4;
            float4 vk = tf4(*reinterpret_cast<const float4*>(Kt + (size_t)r * DKH + c4));
            float4 vv = tf4(*reinterpret_cast<const float4*>(Vt + (size_t)r * DKH + c4));
            *reinterpret_cast<float4*>(Ks + r * KST + c4) = vk;
            *reinterpret_cast<float4*>(Vs + r * VST + c4) = vv;
        }
        __syncthreads();

        // ---- S = Q @ K^T : 8 n-tiles x 16 k-steps ----
        float sfr[8][4];
#pragma unroll
        for (int nt = 0; nt < 8; ++nt)
#pragma unroll
            for (int e = 0; e < 4; ++e) sfr[nt][e] = 0.0f;

        const float* Kb = Ks + grp * KST + kq;
#pragma unroll
        for (int ks = 0; ks < 16; ++ks) {
#pragma unroll
            for (int nt = 0; nt < 8; ++nt) {
                uint32_t b[2];
                const float* p = Kb + nt * (8 * KST) + ks * 8;
                b[0] = fbits(p[0]);
                b[1] = fbits(p[4]);
                mma8(sfr[nt], qa[ks], b);
            }
        }

        // scale + causal mask on diagonal tile
#pragma unroll
        for (int nt = 0; nt < 8; ++nt) {
#pragma unroll
            for (int e = 0; e < 4; ++e) sfr[nt][e] *= sc;
            if (kt == qt) {
                int col = nt * 8 + 2 * kq;
                if (col + 0 > rowlo) sfr[nt][0] = -1e9f;
                if (col + 1 > rowlo) sfr[nt][1] = -1e9f;
                if (col + 0 > rowhi) sfr[nt][2] = -1e9f;
                if (col + 1 > rowhi) sfr[nt][3] = -1e9f;
            }
        }

        // ---- online softmax (rows owned by 4-lane groups) ----
        float mx0 = -1e30f, mx1 = -1e30f;
#pragma unroll
        for (int nt = 0; nt < 8; ++nt) {
            mx0 = fmaxf(mx0, fmaxf(sfr[nt][0], sfr[nt][1]));
            mx1 = fmaxf(mx1, fmaxf(sfr[nt][2], sfr[nt][3]));
        }
        mx0 = fmaxf(mx0, __shfl_xor_sync(0xffffffffu, mx0, 1));
        mx0 = fmaxf(mx0, __shfl_xor_sync(0xffffffffu, mx0, 2));
        mx1 = fmaxf(mx1, __shfl_xor_sync(0xffffffffu, mx1, 1));
        mx1 = fmaxf(mx1, __shfl_xor_sync(0xffffffffu, mx1, 2));

        float mn0 = fmaxf(m0, mx0), mn1 = fmaxf(m1, mx1);
        float c0 = __expf(m0 - mn0), c1 = __expf(m1 - mn1);
        m0 = mn0; m1 = mn1;

        float s0 = 0.0f, s1 = 0.0f;
#pragma unroll
        for (int nt = 0; nt < 8; ++nt) {
            sfr[nt][0] = __expf(sfr[nt][0] - m0);
            sfr[nt][1] = __expf(sfr[nt][1] - m0);
            sfr[nt][2] = __expf(sfr[nt][2] - m1);
            sfr[nt][3] = __expf(sfr[nt][3] - m1);
            s0 += sfr[nt][0] + sfr[nt][1];
            s1 += sfr[nt][2] + sfr[nt][3];
        }
        s0 += __shfl_xor_sync(0xffffffffu, s0, 1);
        s0 += __shfl_xor_sync(0xffffffffu, s0, 2);
        s1 += __shfl_xor_sync(0xffffffffu, s1, 1);
        s1 += __shfl_xor_sync(0xffffffffu, s1, 2);
        l0 = l0 * c0 + s0;
        l1 = l1 * c1 + s1;

#pragma unroll
        for (int nt = 0; nt < 16; ++nt) {
            o[nt][0] *= c0; o[nt][1] *= c0;
            o[nt][2] *= c1; o[nt][3] *= c1;
        }

        // ---- P to warp-private smem ----
        float* Pw = Ps + w * (16 * PST);
#pragma unroll
        for (int nt = 0; nt < 8; ++nt) {
            int col = nt * 8 + 2 * kq;
            float2 plo = make_float2(tf32r(sfr[nt][0]), tf32r(sfr[nt][1]));
            float2 phi = make_float2(tf32r(sfr[nt][2]), tf32r(sfr[nt][3]));
            *reinterpret_cast<float2*>(Pw + grp * PST + col)       = plo;
            *reinterpret_cast<float2*>(Pw + (grp + 8) * PST + col) = phi;
        }
        __syncwarp();

        // ---- O += P @ V : 16 n-tiles x 8 k-steps ----
        const float* Pb = Pw + grp * PST + kq;
        const float* Vb = Vs + kq * VST + grp;
#pragma unroll
        for (int ks = 0; ks < 8; ++ks) {
            uint32_t a[4];
            a[0] = fbits(Pb[ks * 8]);
            a[1] = fbits(Pb[8 * PST + ks * 8]);
            a[2] = fbits(Pb[ks * 8 + 4]);
            a[3] = fbits(Pb[8 * PST + ks * 8 + 4]);
#pragma unroll
            for (int nt = 0; nt < 16; ++nt) {
                uint32_t b[2];
                const float* p = Vb + ks * (8 * VST) + nt * 8;
                b[0] = fbits(p[0]);
                b[1] = fbits(p[4 * VST]);
                mma8(o[nt], a, b);
            }
        }
        __syncwarp();
    }

    // ---- epilogue: normalize, write [B,S,D] ----
    const int b = bh >> 3, h = bh & 7;
    float i0 = 1.0f / l0, i1 = 1.0f / l1;
    int q0 = qt * 64 + rowlo;
    float* r0 = O + ((size_t)b * S_LEN + q0) * DM + h * DKH;
    float* r1 = O + ((size_t)b * S_LEN + q0 + 8) * DM + h * DKH;
#pragma unroll
    for (int nt = 0; nt < 16; ++nt) {
        int col = nt * 8 + 2 * kq;
        *reinterpret_cast<float2*>(r0 + col) = make_float2(o[nt][0] * i0, o[nt][1] * i0);
        *reinterpret_cast<float2*>(r1 + col) = make_float2(o[nt][2] * i1, o[nt][3] * i1);
    }
}

// ---------------------------------------------------------------------------
// Residual + LayerNorm
// ---------------------------------------------------------------------------
__global__ __launch_bounds__(256)
void ln_kernel(const float* __restrict__ Oin, const float* __restrict__ X,
               const float* __restrict__ gamma, const float* __restrict__ beta,
               float* __restrict__ out)
{
    const int r = blockIdx.x;
    const int t = threadIdx.x;

    float4 o = reinterpret_cast<const float4*>(Oin + (size_t)r * DM)[t];
    float4 x = reinterpret_cast<const float4*>(X + (size_t)r * DM)[t];
    float v0 = o.x + x.x, v1 = o.y + x.y, v2 = o.z + x.z, v3 = o.w + x.w;

    float s1 = v0 + v1 + v2 + v3;
    float s2 = v0 * v0 + v1 * v1 + v2 * v2 + v3 * v3;
#pragma unroll
    for (int off = 16; off > 0; off >>= 1) {
        s1 += __shfl_xor_sync(0xffffffffu, s1, off);
        s2 += __shfl_xor_sync(0xffffffffu, s2, off);
    }

    __shared__ float rs1[8], rs2[8], stats[2];
    int warp = t >> 5, lane = t & 31;
    if (lane == 0) { rs1[warp] = s1; rs2[warp] = s2; }
    __syncthreads();
    if (t == 0) {
        float a = 0.0f, b2 = 0.0f;
#pragma unroll
        for (int wdx = 0; wdx < 8; ++wdx) { a += rs1[wdx]; b2 += rs2[wdx]; }
        float mean = a * (1.0f / 1024.0f);
        float var  = b2 * (1.0f / 1024.0f) - mean * mean;
        stats[0] = mean;
        stats[1] = rsqrtf(var + 1e-6f);
    }
    __syncthreads();
    float mean = stats[0], rstd = stats[1];

    float4 g  = reinterpret_cast<const float4*>(gamma)[t];
    float4 bb = reinterpret_cast<const float4*>(beta)[t];
    float4 y;
    y.x = (v0 - mean) * rstd * g.x + bb.x;
    y.y = (v1 - mean) * rstd * g.y + bb.y;
    y.z = (v2 - mean) * rstd * g.z + bb.z;
    y.w = (v3 - mean) * rstd * g.w + bb.w;
    reinterpret_cast<float4*>(out + (size_t)r * DM)[t] = y;
}

// ---------------------------------------------------------------------------
// Launcher
// ---------------------------------------------------------------------------
extern "C" void kernel_launch(void* const* d_in, const int* in_sizes, int n_in,
                              void* d_out, int out_size)
{
    const float* q     = (const float*)d_in[0];
    const float* k     = (const float*)d_in[1];
    const float* v     = (const float*)d_in[2];
    const float* Wq    = (const float*)d_in[3];
    const float* bq    = (const float*)d_in[4];
    const float* Wk    = (const float*)d_in[5];
    const float* bk    = (const float*)d_in[6];
    const float* Wv    = (const float*)d_in[7];
    const float* bv    = (const float*)d_in[8];
    const float* gamma = (const float*)d_in[9];
    const float* beta  = (const float*)d_in[10];
    float* out = (float*)d_out;

    float *Qp, *Kp, *Vp, *Op, *WqT, *WkT, *WvT;
    cudaGetSymbolAddress((void**)&Qp, g_Q);
    cudaGetSymbolAddress((void**)&Kp, g_K);
    cudaGetSymbolAddress((void**)&Vp, g_V);
    cudaGetSymbolAddress((void**)&Op, g_O);
    cudaGetSymbolAddress((void**)&WqT, g_WqT);
    cudaGetSymbolAddress((void**)&WkT, g_WkT);
    cudaGetSymbolAddress((void**)&WvT, g_WvT);

    cudaFuncSetAttribute(gemm_mma, cudaFuncAttributeMaxDynamicSharedMemorySize,
                         GEMM_SMEM);
    cudaFuncSetAttribute(attn_mma, cudaFuncAttributeMaxDynamicSharedMemorySize,
                         ATT_SMEM);

    // W[k][n] -> Wt[n][k]
    dim3 tb(32, 8), tg(32, 32);
    transpose1024<<<tg, tb>>>(Wq, WqT);
    transpose1024<<<tg, tb>>>(Wk, WkT);
    transpose1024<<<tg, tb>>>(Wv, WvT);

    dim3 ggrid(8, 64);
    gemm_mma<<<ggrid, 256, GEMM_SMEM>>>(q, WqT, bq, Qp);
    gemm_mma<<<ggrid, 256, GEMM_SMEM>>>(k, WkT, bk, Kp);
    gemm_mma<<<ggrid, 256, GEMM_SMEM>>>(v, WvT, bv, Vp);

    attn_mma<<<dim3(32, 32), 128, ATT_SMEM>>>(Qp, Kp, Vp, Op);

    ln_kernel<<<8192, 256>>>(Op, q, gamma, beta, out);
}

// round 6
// speedup vs baseline: 6.6641x; 1.6682x over previous
#include <cuda_runtime.h>
#include <cuda_fp16.h>
#include <cstdint>

#define S_LEN 2048
#define B_SZ  4
#define H_NUM 8
#define DKH   128
#define DM    1024

// Scratch (device globals — no allocations allowed)
__device__ __half g_Q[(size_t)B_SZ * H_NUM * S_LEN * DKH];  // [B,H,S,dk] fp16
__device__ __half g_K[(size_t)B_SZ * H_NUM * S_LEN * DKH];
__device__ __half g_V[(size_t)B_SZ * H_NUM * S_LEN * DKH];
__device__ float  g_O[(size_t)B_SZ * S_LEN * DM];           // [B,S,D] fp32
__device__ __half g_WqT[DM * DM];                           // W^T fp16: [n][k]
__device__ __half g_WkT[DM * DM];
__device__ __half g_WvT[DM * DM];

// ---------------------------------------------------------------------------
// helpers
// ---------------------------------------------------------------------------
__device__ __forceinline__ uint32_t h2bits(__half2 h) {
    return *reinterpret_cast<uint32_t*>(&h);
}
__device__ __forceinline__ uint32_t pack2(float lo, float hi) {
    __half2 h = __float22half2_rn(make_float2(lo, hi));
    return h2bits(h);
}

// D += A*B, m16n8k16 fp16 in / fp32 accum (sm_80 baseline; OK on target sm_103)
__device__ __forceinline__ void mma16(float* d, const uint32_t* a, const uint32_t* b) {
    asm volatile(
        "mma.sync.aligned.m16n8k16.row.col.f32.f16.f16.f32 "
        "{%0,%1,%2,%3},{%4,%5,%6,%7},{%8,%9},{%0,%1,%2,%3};"
        : "+f"(d[0]), "+f"(d[1]), "+f"(d[2]), "+f"(d[3])
        : "r"(a[0]), "r"(a[1]), "r"(a[2]), "r"(a[3]), "r"(b[0]), "r"(b[1]));
}

__device__ __forceinline__ uint32_t smem_addr(const void* p) {
    return (uint32_t)__cvta_generic_to_shared(p);
}

// ---------------------------------------------------------------------------
// Tiled transpose + fp16 convert: out[n][k] = half(in[k][n])
// ---------------------------------------------------------------------------
__global__ __launch_bounds__(256)
void transpose_h(const float* __restrict__ in, __half* __restrict__ out)
{
    __shared__ float t[32][33];
    int x  = blockIdx.x * 32 + threadIdx.x;
    int y0 = blockIdx.y * 32;
#pragma unroll
    for (int j = threadIdx.y; j < 32; j += 8)
        t[j][threadIdx.x] = in[(size_t)(y0 + j) * DM + x];
    __syncthreads();
    int x2 = blockIdx.y * 32 + threadIdx.x;
#pragma unroll
    for (int j = threadIdx.y; j < 32; j += 8)
        out[(size_t)(blockIdx.x * 32 + j) * DM + x2] = __float2half(t[threadIdx.x][j]);
}

// ---------------------------------------------------------------------------
// fp16 mma GEMM: Y = X @ W + b. M=8192 N=1024 K=1024.
// A = X[m][k] fp32 gmem (converted inline), B = Wt[n][k] fp16 gmem.
// CTA 128x128, BK=32, 8 warps (64x32 warp tiles), 2-stage smem.
// smem stride 40 halves -> all fragment loads conflict-free.
// Output fp16 into [B,H,S,dk] layout with bias fused.
// ---------------------------------------------------------------------------
#define GST2 40                      // smem row stride (halves)
#define GMAT (128 * GST2)            // halves per matrix per stage (5120)
#define GEMM_SMEM (2 * 2 * GMAT * 2) // 40960 bytes

__global__ __launch_bounds__(256)
void gemm_h(const float* __restrict__ X, const __half* __restrict__ Wt,
            const float* __restrict__ bias, __half* __restrict__ out)
{
    extern __shared__ __half sh[];
    const int tid  = threadIdx.x;
    const int wid  = tid >> 5, lane = tid & 31;
    const int grp  = lane >> 2, kq = lane & 3;
    const int wm   = (wid >> 2) * 64, wn = (wid & 3) * 32;
    const int n0   = blockIdx.x * 128;   // h = blockIdx.x
    const int m0   = blockIdx.y * 128;

    float acc[4][4][4];
#pragma unroll
    for (int mt = 0; mt < 4; ++mt)
#pragma unroll
        for (int nt = 0; nt < 4; ++nt)
#pragma unroll
            for (int e = 0; e < 4; ++e) acc[mt][nt][e] = 0.0f;

    // A: 1024 float4 slots (128 rows x 8 f4); B: 512 uint4 slots (128 rows x 4)
    const int sra[4] = { (tid + 0) >> 3, (tid + 256) >> 3, (tid + 512) >> 3, (tid + 768) >> 3 };
    const int sca    = (tid & 7) * 4;
    const int srb[2] = { (tid + 0) >> 2, (tid + 256) >> 2 };
    const int scb    = (tid & 3) * 8;

    auto stage_store_A = [&](int st, int j, float4 v) {
        uint2 u;
        u.x = pack2(v.x, v.y);
        u.y = pack2(v.z, v.w);
        *reinterpret_cast<uint2*>(sh + st * 2 * GMAT + sra[j] * GST2 + sca) = u;
    };
    auto stage_store_B = [&](int st, int j, uint4 v) {
        *reinterpret_cast<uint4*>(sh + st * 2 * GMAT + GMAT + srb[j] * GST2 + scb) = v;
    };

    // stage 0
#pragma unroll
    for (int j = 0; j < 4; ++j)
        stage_store_A(0, j, *reinterpret_cast<const float4*>(
            X + (size_t)(m0 + sra[j]) * 1024 + sca));
#pragma unroll
    for (int j = 0; j < 2; ++j)
        stage_store_B(0, j, *reinterpret_cast<const uint4*>(
            Wt + (size_t)(n0 + srb[j]) * 1024 + scb));
    __syncthreads();

    float4 pa[4];
    uint4  pb[2];
    for (int i = 0; i < 32; ++i) {
        const __half* Ac = sh + (i & 1) * 2 * GMAT;
        const __half* Bc = Ac + GMAT;

        if (i < 31) {
            const int kn = (i + 1) * 32;
#pragma unroll
            for (int j = 0; j < 4; ++j)
                pa[j] = *reinterpret_cast<const float4*>(
                    X + (size_t)(m0 + sra[j]) * 1024 + kn + sca);
#pragma unroll
            for (int j = 0; j < 2; ++j)
                pb[j] = *reinterpret_cast<const uint4*>(
                    Wt + (size_t)(n0 + srb[j]) * 1024 + kn + scb);
        }

        const __half* Ab = Ac + (wm + grp) * GST2 + 2 * kq;
        const __half* Bb = Bc + (wn + grp) * GST2 + 2 * kq;
#pragma unroll
        for (int ks = 0; ks < 2; ++ks) {
            uint32_t a[4][4], b[4][2];
#pragma unroll
            for (int mt = 0; mt < 4; ++mt) {
                const __half* p = Ab + mt * (16 * GST2) + ks * 16;
                a[mt][0] = *reinterpret_cast<const uint32_t*>(p);
                a[mt][1] = *reinterpret_cast<const uint32_t*>(p + 8 * GST2);
                a[mt][2] = *reinterpret_cast<const uint32_t*>(p + 8);
                a[mt][3] = *reinterpret_cast<const uint32_t*>(p + 8 * GST2 + 8);
            }
#pragma unroll
            for (int nt = 0; nt < 4; ++nt) {
                const __half* p = Bb + nt * (8 * GST2) + ks * 16;
                b[nt][0] = *reinterpret_cast<const uint32_t*>(p);
                b[nt][1] = *reinterpret_cast<const uint32_t*>(p + 8);
            }
#pragma unroll
            for (int mt = 0; mt < 4; ++mt)
#pragma unroll
                for (int nt = 0; nt < 4; ++nt)
                    mma16(acc[mt][nt], a[mt], b[nt]);
        }

        if (i < 31) {
            const int st = (i + 1) & 1;
#pragma unroll
            for (int j = 0; j < 4; ++j) stage_store_A(st, j, pa[j]);
#pragma unroll
            for (int j = 0; j < 2; ++j) stage_store_B(st, j, pb[j]);
        }
        __syncthreads();
    }

    // epilogue: bias + fp16 head-split store ([B,H,S,dk])
    const int h = blockIdx.x;
#pragma unroll
    for (int mt = 0; mt < 4; ++mt) {
#pragma unroll
        for (int half_ = 0; half_ < 2; ++half_) {
            int m = m0 + wm + mt * 16 + grp + half_ * 8;
            int b = m >> 11, s = m & 2047;
            __half* orow = out + (((size_t)b * H_NUM + h) * S_LEN + s) * DKH;
#pragma unroll
            for (int nt = 0; nt < 4; ++nt) {
                int nl = wn + nt * 8 + 2 * kq;
                float2 bv = *reinterpret_cast<const float2*>(bias + n0 + nl);
                uint32_t u = pack2(acc[mt][nt][half_ * 2 + 0] + bv.x,
                                   acc[mt][nt][half_ * 2 + 1] + bv.y);
                *reinterpret_cast<uint32_t*>(orow + nl) = u;
            }
        }
    }
}

// ---------------------------------------------------------------------------
// Flash attention on fp16 mma. BQ=64, BKV=64, dk=128, 4 warps.
// Q A-fragments in registers. S-phase: direct smem frag loads (stride 136,
// conflict-free). PV-phase: ldmatrix.x4.trans on row-major V tile.
// ---------------------------------------------------------------------------
#define KST2 136
#define VST2 136
#define PST2 72
#define ATT_KS 0
#define ATT_VS (64 * KST2)                   // 8704
#define ATT_PS (ATT_VS + 64 * VST2)          // 17408
#define ATT_HALVES (ATT_PS + 4 * 16 * PST2)  // 22016
#define ATT_SMEM (ATT_HALVES * 2)            // 44032 bytes

__global__ __launch_bounds__(128)
void attn_h(const __half* __restrict__ Q, const __half* __restrict__ K,
            const __half* __restrict__ V, float* __restrict__ O)
{
    extern __shared__ __half sa[];
    __half* Ks = sa + ATT_KS;
    __half* Vs = sa + ATT_VS;
    __half* Ps = sa + ATT_PS;

    const int qt  = (int)gridDim.x - 1 - (int)blockIdx.x;  // heavy tiles first
    const int bh  = blockIdx.y;
    const int tid = threadIdx.x;
    const int w   = tid >> 5, lane = tid & 31;
    const int grp = lane >> 2, kq = lane & 3;

    const __half* Qg = Q + ((size_t)bh * S_LEN + (size_t)qt * 64) * DKH;
    const __half* Kg = K + (size_t)bh * S_LEN * DKH;
    const __half* Vg = V + (size_t)bh * S_LEN * DKH;

    // ---- stage Q into Ks area, pull A-fragments to registers ----
#pragma unroll
    for (int j = 0; j < 8; ++j) {
        int s = tid + j * 128;
        int r = s >> 4, c8 = (s & 15) * 8;
        *reinterpret_cast<uint4*>(Ks + r * KST2 + c8) =
            *reinterpret_cast<const uint4*>(Qg + (size_t)r * DKH + c8);
    }
    __syncthreads();

    uint32_t qa[8][4];
    {
        const __half* qb = Ks + (w * 16 + grp) * KST2 + 2 * kq;
#pragma unroll
        for (int ks = 0; ks < 8; ++ks) {
            qa[ks][0] = *reinterpret_cast<const uint32_t*>(qb + ks * 16);
            qa[ks][1] = *reinterpret_cast<const uint32_t*>(qb + 8 * KST2 + ks * 16);
            qa[ks][2] = *reinterpret_cast<const uint32_t*>(qb + ks * 16 + 8);
            qa[ks][3] = *reinterpret_cast<const uint32_t*>(qb + 8 * KST2 + ks * 16 + 8);
        }
    }

    float o[16][4];
#pragma unroll
    for (int nt = 0; nt < 16; ++nt)
#pragma unroll
        for (int e = 0; e < 4; ++e) o[nt][e] = 0.0f;
    float m0 = -1e30f, m1 = -1e30f, l0 = 0.0f, l1 = 0.0f;

    const float sc = 0.08838834764831843f;  // 1/sqrt(128)
    const int rowlo = w * 16 + grp;
    const int rowhi = rowlo + 8;

    for (int kt = 0; kt <= qt; ++kt) {
        __syncthreads();   // prior iter done with Ks/Vs (and Q staging)

        const __half* Kt = Kg + (size_t)kt * 64 * DKH;
        const __half* Vt = Vg + (size_t)kt * 64 * DKH;
#pragma unroll
        for (int j = 0; j < 8; ++j) {
            int s = tid + j * 128;
            int r = s >> 4, c8 = (s & 15) * 8;
            *reinterpret_cast<uint4*>(Ks + r * KST2 + c8) =
                *reinterpret_cast<const uint4*>(Kt + (size_t)r * DKH + c8);
            *reinterpret_cast<uint4*>(Vs + r * VST2 + c8) =
                *reinterpret_cast<const uint4*>(Vt + (size_t)r * DKH + c8);
        }
        __syncthreads();

        // ---- S = Q @ K^T : 8 n-tiles x 8 k16-steps ----
        float sfr[8][4];
#pragma unroll
        for (int nt = 0; nt < 8; ++nt)
#pragma unroll
            for (int e = 0; e < 4; ++e) sfr[nt][e] = 0.0f;

        const __half* Kb = Ks + grp * KST2 + 2 * kq;
#pragma unroll
        for (int ks = 0; ks < 8; ++ks) {
#pragma unroll
            for (int nt = 0; nt < 8; ++nt) {
                uint32_t b[2];
                const __half* p = Kb + nt * (8 * KST2) + ks * 16;
                b[0] = *reinterpret_cast<const uint32_t*>(p);
                b[1] = *reinterpret_cast<const uint32_t*>(p + 8);
                mma16(sfr[nt], qa[ks], b);
            }
        }

        // scale + causal mask on diagonal tile
#pragma unroll
        for (int nt = 0; nt < 8; ++nt) {
#pragma unroll
            for (int e = 0; e < 4; ++e) sfr[nt][e] *= sc;
            if (kt == qt) {
                int col = nt * 8 + 2 * kq;
                if (col + 0 > rowlo) sfr[nt][0] = -1e9f;
                if (col + 1 > rowlo) sfr[nt][1] = -1e9f;
                if (col + 0 > rowhi) sfr[nt][2] = -1e9f;
                if (col + 1 > rowhi) sfr[nt][3] = -1e9f;
            }
        }

        // ---- online softmax ----
        float mx0 = -1e30f, mx1 = -1e30f;
#pragma unroll
        for (int nt = 0; nt < 8; ++nt) {
            mx0 = fmaxf(mx0, fmaxf(sfr[nt][0], sfr[nt][1]));
            mx1 = fmaxf(mx1, fmaxf(sfr[nt][2], sfr[nt][3]));
        }
        mx0 = fmaxf(mx0, __shfl_xor_sync(0xffffffffu, mx0, 1));
        mx0 = fmaxf(mx0, __shfl_xor_sync(0xffffffffu, mx0, 2));
        mx1 = fmaxf(mx1, __shfl_xor_sync(0xffffffffu, mx1, 1));
        mx1 = fmaxf(mx1, __shfl_xor_sync(0xffffffffu, mx1, 2));

        float mn0 = fmaxf(m0, mx0), mn1 = fmaxf(m1, mx1);
        float c0 = __expf(m0 - mn0), c1 = __expf(m1 - mn1);
        m0 = mn0; m1 = mn1;

        float s0 = 0.0f, s1 = 0.0f;
#pragma unroll
        for (int nt = 0; nt < 8; ++nt) {
            sfr[nt][0] = __expf(sfr[nt][0] - m0);
            sfr[nt][1] = __expf(sfr[nt][1] - m0);
            sfr[nt][2] = __expf(sfr[nt][2] - m1);
            sfr[nt][3] = __expf(sfr[nt][3] - m1);
            s0 += sfr[nt][0] + sfr[nt][1];
            s1 += sfr[nt][2] + sfr[nt][3];
        }
        s0 += __shfl_xor_sync(0xffffffffu, s0, 1);
        s0 += __shfl_xor_sync(0xffffffffu, s0, 2);
        s1 += __shfl_xor_sync(0xffffffffu, s1, 1);
        s1 += __shfl_xor_sync(0xffffffffu, s1, 2);
        l0 = l0 * c0 + s0;
        l1 = l1 * c1 + s1;

#pragma unroll
        for (int nt = 0; nt < 16; ++nt) {
            o[nt][0] *= c0; o[nt][1] *= c0;
            o[nt][2] *= c1; o[nt][3] *= c1;
        }

        // ---- P (fp16) to warp-private smem ----
        __half* Pw = Ps + w * (16 * PST2);
#pragma unroll
        for (int nt = 0; nt < 8; ++nt) {
            int col = nt * 8 + 2 * kq;
            *reinterpret_cast<uint32_t*>(Pw + grp * PST2 + col) =
                pack2(sfr[nt][0], sfr[nt][1]);
            *reinterpret_cast<uint32_t*>(Pw + (grp + 8) * PST2 + col) =
                pack2(sfr[nt][2], sfr[nt][3]);
        }
        __syncwarp();

        // ---- O += P @ V : 4 k16-steps, ldmatrix.trans B frags ----
        const __half* Pb = Pw + grp * PST2 + 2 * kq;
        const int lrow = ((lane >> 3) & 1) * 8 + (lane & 7);
        const int lcol = (lane >> 4) * 8;
#pragma unroll
        for (int ks = 0; ks < 4; ++ks) {
            uint32_t a[4];
            a[0] = *reinterpret_cast<const uint32_t*>(Pb + ks * 16);
            a[1] = *reinterpret_cast<const uint32_t*>(Pb + 8 * PST2 + ks * 16);
            a[2] = *reinterpret_cast<const uint32_t*>(Pb + ks * 16 + 8);
            a[3] = *reinterpret_cast<const uint32_t*>(Pb + 8 * PST2 + ks * 16 + 8);
            const __half* vrow = Vs + (ks * 16 + lrow) * VST2 + lcol;
#pragma unroll
            for (int ntp = 0; ntp < 8; ++ntp) {
                uint32_t r0, r1, r2, r3;
                uint32_t ad = smem_addr(vrow + ntp * 16);
                asm volatile(
                    "ldmatrix.sync.aligned.m8n8.x4.trans.shared.b16 "
                    "{%0,%1,%2,%3}, [%4];"
                    : "=r"(r0), "=r"(r1), "=r"(r2), "=r"(r3) : "r"(ad));
                uint32_t b0[2] = { r0, r1 }, b1[2] = { r2, r3 };
                mma16(o[2 * ntp + 0], a, b0);
                mma16(o[2 * ntp + 1], a, b1);
            }
        }
        __syncwarp();
    }

    // ---- epilogue: normalize, write fp32 [B,S,D] ----
    const int b = bh >> 3, h = bh & 7;
    float i0 = 1.0f / l0, i1 = 1.0f / l1;
    int q0 = qt * 64 + rowlo;
    float* r0 = O + ((size_t)b * S_LEN + q0) * DM + h * DKH;
    float* r1 = O + ((size_t)b * S_LEN + q0 + 8) * DM + h * DKH;
#pragma unroll
    for (int nt = 0; nt < 16; ++nt) {
        int col = nt * 8 + 2 * kq;
        *reinterpret_cast<float2*>(r0 + col) = make_float2(o[nt][0] * i0, o[nt][1] * i0);
        *reinterpret_cast<float2*>(r1 + col) = make_float2(o[nt][2] * i1, o[nt][3] * i1);
    }
}

// ---------------------------------------------------------------------------
// Residual + LayerNorm
// ---------------------------------------------------------------------------
__global__ __launch_bounds__(256)
void ln_kernel(const float* __restrict__ Oin, const float* __restrict__ X,
               const float* __restrict__ gamma, const float* __restrict__ beta,
               float* __restrict__ out)
{
    const int r = blockIdx.x;
    const int t = threadIdx.x;

    float4 o = reinterpret_cast<const float4*>(Oin + (size_t)r * DM)[t];
    float4 x = reinterpret_cast<const float4*>(X + (size_t)r * DM)[t];
    float v0 = o.x + x.x, v1 = o.y + x.y, v2 = o.z + x.z, v3 = o.w + x.w;

    float s1 = v0 + v1 + v2 + v3;
    float s2 = v0 * v0 + v1 * v1 + v2 * v2 + v3 * v3;
#pragma unroll
    for (int off = 16; off > 0; off >>= 1) {
        s1 += __shfl_xor_sync(0xffffffffu, s1, off);
        s2 += __shfl_xor_sync(0xffffffffu, s2, off);
    }

    __shared__ float rs1[8], rs2[8], stats[2];
    int warp = t >> 5, lane = t & 31;
    if (lane == 0) { rs1[warp] = s1; rs2[warp] = s2; }
    __syncthreads();
    if (t == 0) {
        float a = 0.0f, b2 = 0.0f;
#pragma unroll
        for (int wdx = 0; wdx < 8; ++wdx) { a += rs1[wdx]; b2 += rs2[wdx]; }
        float mean = a * (1.0f / 1024.0f);
        float var  = b2 * (1.0f / 1024.0f) - mean * mean;
        stats[0] = mean;
        stats[1] = rsqrtf(var + 1e-6f);
    }
    __syncthreads();
    float mean = stats[0], rstd = stats[1];

    float4 g  = reinterpret_cast<const float4*>(gamma)[t];
    float4 bb = reinterpret_cast<const float4*>(beta)[t];
    float4 y;
    y.x = (v0 - mean) * rstd * g.x + bb.x;
    y.y = (v1 - mean) * rstd * g.y + bb.y;
    y.z = (v2 - mean) * rstd * g.z + bb.z;
    y.w = (v3 - mean) * rstd * g.w + bb.w;
    reinterpret_cast<float4*>(out + (size_t)r * DM)[t] = y;
}

// ---------------------------------------------------------------------------
// Launcher
// ---------------------------------------------------------------------------
extern "C" void kernel_launch(void* const* d_in, const int* in_sizes, int n_in,
                              void* d_out, int out_size)
{
    const float* q     = (const float*)d_in[0];
    const float* k     = (const float*)d_in[1];
    const float* v     = (const float*)d_in[2];
    const float* Wq    = (const float*)d_in[3];
    const float* bq    = (const float*)d_in[4];
    const float* Wk    = (const float*)d_in[5];
    const float* bk    = (const float*)d_in[6];
    const float* Wv    = (const float*)d_in[7];
    const float* bv    = (const float*)d_in[8];
    const float* gamma = (const float*)d_in[9];
    const float* beta  = (const float*)d_in[10];
    float* out = (float*)d_out;

    __half *Qp, *Kp, *Vp, *WqT, *WkT, *WvT;
    float *Op;
    cudaGetSymbolAddress((void**)&Qp, g_Q);
    cudaGetSymbolAddress((void**)&Kp, g_K);
    cudaGetSymbolAddress((void**)&Vp, g_V);
    cudaGetSymbolAddress((void**)&Op, g_O);
    cudaGetSymbolAddress((void**)&WqT, g_WqT);
    cudaGetSymbolAddress((void**)&WkT, g_WkT);
    cudaGetSymbolAddress((void**)&WvT, g_WvT);

    cudaFuncSetAttribute(gemm_h, cudaFuncAttributeMaxDynamicSharedMemorySize,
                         GEMM_SMEM);
    cudaFuncSetAttribute(attn_h, cudaFuncAttributeMaxDynamicSharedMemorySize,
                         ATT_SMEM);

    // W[k][n] -> W^T[n][k] (fp16)
    dim3 tb(32, 8), tg(32, 32);
    transpose_h<<<tg, tb>>>(Wq, WqT);
    transpose_h<<<tg, tb>>>(Wk, WkT);
    transpose_h<<<tg, tb>>>(Wv, WvT);

    dim3 ggrid(8, 64);
    gemm_h<<<ggrid, 256, GEMM_SMEM>>>(q, WqT, bq, Qp);
    gemm_h<<<ggrid, 256, GEMM_SMEM>>>(k, WkT, bk, Kp);
    gemm_h<<<ggrid, 256, GEMM_SMEM>>>(v, WvT, bv, Vp);

    attn_h<<<dim3(32, 32), 128, ATT_SMEM>>>(Qp, Kp, Vp, Op);

    ln_kernel<<<8192, 256>>>(Op, q, gamma, beta, out);
}

// round 7
// speedup vs baseline: 7.0218x; 1.0537x over previous
#include <cuda_runtime.h>
#include <cuda_fp16.h>
#include <cstdint>

#define S_LEN 2048
#define B_SZ  4
#define H_NUM 8
#define DKH   128
#define DM    1024

// Scratch (device globals — no allocations allowed)
__device__ __half g_Q[(size_t)B_SZ * H_NUM * S_LEN * DKH];  // [B,H,S,dk] fp16
__device__ __half g_K[(size_t)B_SZ * H_NUM * S_LEN * DKH];
__device__ __half g_V[(size_t)B_SZ * H_NUM * S_LEN * DKH];
__device__ float  g_O[(size_t)B_SZ * S_LEN * DM];           // [B,S,D] fp32
__device__ __half g_WqT[DM * DM];                           // W^T fp16: [n][k]
__device__ __half g_WkT[DM * DM];
__device__ __half g_WvT[DM * DM];
__device__ __half g_qh[(size_t)B_SZ * S_LEN * DM];          // fp16 copies of inputs
__device__ __half g_kh[(size_t)B_SZ * S_LEN * DM];
__device__ __half g_vh[(size_t)B_SZ * S_LEN * DM];

// ---------------------------------------------------------------------------
// helpers
// ---------------------------------------------------------------------------
__device__ __forceinline__ uint32_t pack2(float lo, float hi) {
    __half2 h = __float22half2_rn(make_float2(lo, hi));
    return *reinterpret_cast<uint32_t*>(&h);
}
__device__ __forceinline__ uint32_t smem_addr(const void* p) {
    return (uint32_t)__cvta_generic_to_shared(p);
}
__device__ __forceinline__ void cpa16(uint32_t dst, const void* src) {
    asm volatile("cp.async.cg.shared.global [%0], [%1], 16;" :: "r"(dst), "l"(src));
}
#define CP_COMMIT() asm volatile("cp.async.commit_group;" ::: "memory")
#define CP_WAIT(n)  asm volatile("cp.async.wait_group %0;" :: "n"(n) : "memory")

// D += A*B, m16n8k16 fp16 in / fp32 accum
__device__ __forceinline__ void mma16(float* d, const uint32_t* a, const uint32_t* b) {
    asm volatile(
        "mma.sync.aligned.m16n8k16.row.col.f32.f16.f16.f32 "
        "{%0,%1,%2,%3},{%4,%5,%6,%7},{%8,%9},{%0,%1,%2,%3};"
        : "+f"(d[0]), "+f"(d[1]), "+f"(d[2]), "+f"(d[3])
        : "r"(a[0]), "r"(a[1]), "r"(a[2]), "r"(a[3]), "r"(b[0]), "r"(b[1]));
}
#define LDSM4(r, addr)                                                        \
    asm volatile("ldmatrix.sync.aligned.m8n8.x4.shared.b16 {%0,%1,%2,%3},[%4];" \
        : "=r"((r)[0]), "=r"((r)[1]), "=r"((r)[2]), "=r"((r)[3]) : "r"(addr))
#define LDSM4T(r, addr)                                                       \
    asm volatile("ldmatrix.sync.aligned.m8n8.x4.trans.shared.b16 {%0,%1,%2,%3},[%4];" \
        : "=r"((r)[0]), "=r"((r)[1]), "=r"((r)[2]), "=r"((r)[3]) : "r"(addr))

// ---------------------------------------------------------------------------
// fp32 -> fp16 convert (each thread: 1 float4 -> 4 halves)
// ---------------------------------------------------------------------------
__global__ __launch_bounds__(256)
void f2h(const float4* __restrict__ in, uint2* __restrict__ out)
{
    size_t i = (size_t)blockIdx.x * 256 + threadIdx.x;
    float4 v = in[i];
    uint2 u;
    u.x = pack2(v.x, v.y);
    u.y = pack2(v.z, v.w);
    out[i] = u;
}

// ---------------------------------------------------------------------------
// Tiled transpose + fp16 convert: out[n][k] = half(in[k][n])
// ---------------------------------------------------------------------------
__global__ __launch_bounds__(256)
void transpose_h(const float* __restrict__ in, __half* __restrict__ out)
{
    __shared__ float t[32][33];
    int x  = blockIdx.x * 32 + threadIdx.x;
    int y0 = blockIdx.y * 32;
#pragma unroll
    for (int j = threadIdx.y; j < 32; j += 8)
        t[j][threadIdx.x] = in[(size_t)(y0 + j) * DM + x];
    __syncthreads();
    int x2 = blockIdx.y * 32 + threadIdx.x;
#pragma unroll
    for (int j = threadIdx.y; j < 32; j += 8)
        out[(size_t)(blockIdx.x * 32 + j) * DM + x2] = __float2half(t[threadIdx.x][j]);
}

// ---------------------------------------------------------------------------
// fp16 mma GEMM with cp.async 3-stage pipeline + ldmatrix fragments.
// Y = Xh @ W + b. M=8192 N=1024 K=1024. A=Xh[m][k], B=Wt[n][k] (fp16 K-major).
// CTA 128x128, BK=32, 8 warps (64x32 warp tiles).
// smem row stride 40 halves (80 B): ldmatrix phases conflict-free.
// ---------------------------------------------------------------------------
#define GROWB  80                         // bytes per smem row
#define AMAT_B (128 * GROWB)              // 10240 bytes per matrix
#define STAGE_B (2 * AMAT_B)              // 20480 per stage
#define GEMM_SMEM (3 * STAGE_B)           // 61440 bytes

__global__ __launch_bounds__(256)
void gemm_h2(const __half* __restrict__ Xh, const __half* __restrict__ Wt,
             const float* __restrict__ bias, __half* __restrict__ out)
{
    extern __shared__ __align__(16) char sm_raw[];
    const uint32_t sb = smem_addr(sm_raw);
    const int tid  = threadIdx.x;
    const int wid  = tid >> 5, lane = tid & 31;
    const int grp  = lane >> 2, kq = lane & 3;
    const int wm   = (wid >> 2) * 64, wn = (wid & 3) * 32;
    const int n0   = blockIdx.x * 128;   // h = blockIdx.x
    const int m0   = blockIdx.y * 128;

    float acc[4][4][4];
#pragma unroll
    for (int mt = 0; mt < 4; ++mt)
#pragma unroll
        for (int nt = 0; nt < 4; ++nt)
#pragma unroll
            for (int e = 0; e < 4; ++e) acc[mt][nt][e] = 0.0f;

    // cp.async tile loader: 512 16B chunks per matrix, 2 per thread
    auto load_stage = [&](int st, int kt) {
        const uint32_t base = sb + st * STAGE_B;
        const __half* Ag = Xh + (size_t)m0 * 1024 + kt * 32;
        const __half* Bg = Wt + (size_t)n0 * 1024 + kt * 32;
#pragma unroll
        for (int t = 0; t < 2; ++t) {
            int idx = tid + t * 256;          // 0..511
            int r = idx >> 2, c = idx & 3;
            cpa16(base + r * GROWB + c * 16,          Ag + (size_t)r * 1024 + c * 8);
            cpa16(base + AMAT_B + r * GROWB + c * 16, Bg + (size_t)r * 1024 + c * 8);
        }
    };

    // ldmatrix per-lane addressing
    const int arow = wm + ((lane >> 3) & 1) * 8 + (lane & 7);
    const int acol = (lane >> 4) * 8;                  // halves
    const int brow = wn + ((lane >> 4) & 1) * 8 + (lane & 7);
    const int bcol = ((lane >> 3) & 1) * 8;

    load_stage(0, 0); CP_COMMIT();
    load_stage(1, 1); CP_COMMIT();
    load_stage(2, 2); CP_COMMIT();

    int st = 0;
    for (int i = 0; i < 32; ++i) {
        CP_WAIT(2);
        __syncthreads();

        const uint32_t Ac = sb + st * STAGE_B;
        const uint32_t Bc = Ac + AMAT_B;
#pragma unroll
        for (int ks = 0; ks < 2; ++ks) {
            uint32_t a[4][4], b[2][4];
#pragma unroll
            for (int mt = 0; mt < 4; ++mt)
                LDSM4(a[mt], Ac + (arow + mt * 16) * GROWB + (ks * 16 + acol) * 2);
#pragma unroll
            for (int ntp = 0; ntp < 2; ++ntp)
                LDSM4(b[ntp], Bc + (brow + ntp * 16) * GROWB + (ks * 16 + bcol) * 2);
#pragma unroll
            for (int mt = 0; mt < 4; ++mt) {
                mma16(acc[mt][0], a[mt], &b[0][0]);
                mma16(acc[mt][1], a[mt], &b[0][2]);
                mma16(acc[mt][2], a[mt], &b[1][0]);
                mma16(acc[mt][3], a[mt], &b[1][2]);
            }
        }
        __syncthreads();
        if (i + 3 < 32) load_stage(st, i + 3);
        CP_COMMIT();
        st = (st == 2) ? 0 : st + 1;
    }

    // epilogue: bias + fp16 head-split store ([B,H,S,dk])
    const int h = blockIdx.x;
#pragma unroll
    for (int mt = 0; mt < 4; ++mt) {
#pragma unroll
        for (int half_ = 0; half_ < 2; ++half_) {
            int m = m0 + wm + mt * 16 + grp + half_ * 8;
            int b = m >> 11, s = m & 2047;
            __half* orow = out + (((size_t)b * H_NUM + h) * S_LEN + s) * DKH;
#pragma unroll
            for (int nt = 0; nt < 4; ++nt) {
                int nl = wn + nt * 8 + 2 * kq;
                float2 bv = *reinterpret_cast<const float2*>(bias + n0 + nl);
                uint32_t u = pack2(acc[mt][nt][half_ * 2 + 0] + bv.x,
                                   acc[mt][nt][half_ * 2 + 1] + bv.y);
                *reinterpret_cast<uint32_t*>(orow + nl) = u;
            }
        }
    }
}

// ---------------------------------------------------------------------------
// Flash attention, fp16 mma. BQ=64, BKV=64, dk=128, 4 warps.
// cp.async K/V tile loads; ldmatrix for K (S-phase B), P (PV A), V (PV B, trans).
// ---------------------------------------------------------------------------
#define KST2 136
#define VST2 136
#define PST2 72
#define ATT_KS 0
#define ATT_VS (64 * KST2)                   // 8704
#define ATT_PS (ATT_VS + 64 * VST2)          // 17408
#define ATT_HALVES (ATT_PS + 4 * 16 * PST2)  // 22016
#define ATT_SMEM (ATT_HALVES * 2)            // 44032 bytes

__global__ __launch_bounds__(128)
void attn_h(const __half* __restrict__ Q, const __half* __restrict__ K,
            const __half* __restrict__ V, float* __restrict__ O)
{
    extern __shared__ __half sa[];
    __half* Ks = sa + ATT_KS;
    __half* Vs = sa + ATT_VS;
    __half* Ps = sa + ATT_PS;
    const uint32_t Ksb = smem_addr(Ks);
    const uint32_t Vsb = smem_addr(Vs);

    const int qt  = (int)gridDim.x - 1 - (int)blockIdx.x;  // heavy tiles first
    const int bh  = blockIdx.y;
    const int tid = threadIdx.x;
    const int w   = tid >> 5, lane = tid & 31;
    const int grp = lane >> 2, kq = lane & 3;

    const __half* Qg = Q + ((size_t)bh * S_LEN + (size_t)qt * 64) * DKH;
    const __half* Kg = K + (size_t)bh * S_LEN * DKH;
    const __half* Vg = V + (size_t)bh * S_LEN * DKH;

    // ---- stage Q into Ks area, pull A-fragments to registers ----
#pragma unroll
    for (int j = 0; j < 8; ++j) {
        int s = tid + j * 128;
        int r = s >> 4, c8 = (s & 15) * 8;
        *reinterpret_cast<uint4*>(Ks + r * KST2 + c8) =
            *reinterpret_cast<const uint4*>(Qg + (size_t)r * DKH + c8);
    }
    __syncthreads();

    uint32_t qa[8][4];
    {
        // A-frag ldmatrix addressing on Q tile (rows w*16..w*16+15)
        const int qrow = w * 16 + ((lane >> 3) & 1) * 8 + (lane & 7);
        const int qcol = (lane >> 4) * 8;
#pragma unroll
        for (int ks = 0; ks < 8; ++ks)
            LDSM4(qa[ks], Ksb + (qrow * KST2 + ks * 16 + qcol) * 2);
    }

    float o[16][4];
#pragma unroll
    for (int nt = 0; nt < 16; ++nt)
#pragma unroll
        for (int e = 0; e < 4; ++e) o[nt][e] = 0.0f;
    float m0 = -1e30f, m1 = -1e30f, l0 = 0.0f, l1 = 0.0f;

    const float sc = 0.08838834764831843f;  // 1/sqrt(128)
    const int rowlo = w * 16 + grp;
    const int rowhi = rowlo + 8;

    // ldmatrix lane addressing (reused per iter)
    const int krow_l = ((lane >> 4) & 1) * 8 + (lane & 7);   // K B-frag rows
    const int kcol_l = ((lane >> 3) & 1) * 8;
    const int prow_l = ((lane >> 3) & 1) * 8 + (lane & 7);   // P A-frag rows
    const int pcol_l = (lane >> 4) * 8;
    const int lrow   = ((lane >> 3) & 1) * 8 + (lane & 7);   // V trans rows
    const int lcol   = (lane >> 4) * 8;

    for (int kt = 0; kt <= qt; ++kt) {
        __syncthreads();   // prior iter done with Ks/Vs (and Q staging/frags)

        const __half* Kt = Kg + (size_t)kt * 64 * DKH;
        const __half* Vt = Vg + (size_t)kt * 64 * DKH;
#pragma unroll
        for (int j = 0; j < 8; ++j) {
            int idx = tid + j * 128;
            int r = idx >> 4, c = idx & 15;
            cpa16(Ksb + r * (KST2 * 2) + c * 16, Kt + (size_t)r * DKH + c * 8);
            cpa16(Vsb + r * (VST2 * 2) + c * 16, Vt + (size_t)r * DKH + c * 8);
        }
        CP_COMMIT();
        CP_WAIT(0);
        __syncthreads();

        // ---- S = Q @ K^T : 8 k16-steps x 4 nt-pairs (ldmatrix.x4) ----
        float sfr[8][4];
#pragma unroll
        for (int nt = 0; nt < 8; ++nt)
#pragma unroll
            for (int e = 0; e < 4; ++e) sfr[nt][e] = 0.0f;

#pragma unroll
        for (int ks = 0; ks < 8; ++ks) {
#pragma unroll
            for (int ntp = 0; ntp < 4; ++ntp) {
                uint32_t bb[4];
                LDSM4(bb, Ksb + ((ntp * 16 + krow_l) * KST2 + ks * 16 + kcol_l) * 2);
                mma16(sfr[2 * ntp + 0], qa[ks], &bb[0]);
                mma16(sfr[2 * ntp + 1], qa[ks], &bb[2]);
            }
        }

        // scale + causal mask on diagonal tile
#pragma unroll
        for (int nt = 0; nt < 8; ++nt) {
#pragma unroll
            for (int e = 0; e < 4; ++e) sfr[nt][e] *= sc;
            if (kt == qt) {
                int col = nt * 8 + 2 * kq;
                if (col + 0 > rowlo) sfr[nt][0] = -1e9f;
                if (col + 1 > rowlo) sfr[nt][1] = -1e9f;
                if (col + 0 > rowhi) sfr[nt][2] = -1e9f;
                if (col + 1 > rowhi) sfr[nt][3] = -1e9f;
            }
        }

        // ---- online softmax ----
        float mx0 = -1e30f, mx1 = -1e30f;
#pragma unroll
        for (int nt = 0; nt < 8; ++nt) {
            mx0 = fmaxf(mx0, fmaxf(sfr[nt][0], sfr[nt][1]));
            mx1 = fmaxf(mx1, fmaxf(sfr[nt][2], sfr[nt][3]));
        }
        mx0 = fmaxf(mx0, __shfl_xor_sync(0xffffffffu, mx0, 1));
        mx0 = fmaxf(mx0, __shfl_xor_sync(0xffffffffu, mx0, 2));
        mx1 = fmaxf(mx1, __shfl_xor_sync(0xffffffffu, mx1, 1));
        mx1 = fmaxf(mx1, __shfl_xor_sync(0xffffffffu, mx1, 2));

        float mn0 = fmaxf(m0, mx0), mn1 = fmaxf(m1, mx1);
        float c0 = __expf(m0 - mn0), c1 = __expf(m1 - mn1);
        m0 = mn0; m1 = mn1;

        float s0 = 0.0f, s1 = 0.0f;
#pragma unroll
        for (int nt = 0; nt < 8; ++nt) {
            sfr[nt][0] = __expf(sfr[nt][0] - m0);
            sfr[nt][1] = __expf(sfr[nt][1] - m0);
            sfr[nt][2] = __expf(sfr[nt][2] - m1);
            sfr[nt][3] = __expf(sfr[nt][3] - m1);
            s0 += sfr[nt][0] + sfr[nt][1];
            s1 += sfr[nt][2] + sfr[nt][3];
        }
        s0 += __shfl_xor_sync(0xffffffffu, s0, 1);
        s0 += __shfl_xor_sync(0xffffffffu, s0, 2);
        s1 += __shfl_xor_sync(0xffffffffu, s1, 1);
        s1 += __shfl_xor_sync(0xffffffffu, s1, 2);
        l0 = l0 * c0 + s0;
        l1 = l1 * c1 + s1;

#pragma unroll
        for (int nt = 0; nt < 16; ++nt) {
            o[nt][0] *= c0; o[nt][1] *= c0;
            o[nt][2] *= c1; o[nt][3] *= c1;
        }

        // ---- P (fp16) to warp-private smem ----
        __half* Pw = Ps + w * (16 * PST2);
        const uint32_t Pwb = smem_addr(Pw);
#pragma unroll
        for (int nt = 0; nt < 8; ++nt) {
            int col = nt * 8 + 2 * kq;
            *reinterpret_cast<uint32_t*>(Pw + grp * PST2 + col) =
                pack2(sfr[nt][0], sfr[nt][1]);
            *reinterpret_cast<uint32_t*>(Pw + (grp + 8) * PST2 + col) =
                pack2(sfr[nt][2], sfr[nt][3]);
        }
        __syncwarp();

        // ---- O += P @ V : 4 k16-steps; P via ldmatrix, V via ldmatrix.trans ----
#pragma unroll
        for (int ks = 0; ks < 4; ++ks) {
            uint32_t a[4];
            LDSM4(a, Pwb + (prow_l * PST2 + ks * 16 + pcol_l) * 2);
            const uint32_t vbase = Vsb + ((ks * 16 + lrow) * VST2 + lcol) * 2;
#pragma unroll
            for (int ntp = 0; ntp < 8; ++ntp) {
                uint32_t bb[4];
                LDSM4T(bb, vbase + ntp * 32);
                mma16(o[2 * ntp + 0], a, &bb[0]);
                mma16(o[2 * ntp + 1], a, &bb[2]);
            }
        }
        __syncwarp();
    }

    // ---- epilogue: normalize, write fp32 [B,S,D] ----
    const int b = bh >> 3, h = bh & 7;
    float i0 = 1.0f / l0, i1 = 1.0f / l1;
    int q0 = qt * 64 + rowlo;
    float* r0 = O + ((size_t)b * S_LEN + q0) * DM + h * DKH;
    float* r1 = O + ((size_t)b * S_LEN + q0 + 8) * DM + h * DKH;
#pragma unroll
    for (int nt = 0; nt < 16; ++nt) {
        int col = nt * 8 + 2 * kq;
        *reinterpret_cast<float2*>(r0 + col) = make_float2(o[nt][0] * i0, o[nt][1] * i0);
        *reinterpret_cast<float2*>(r1 + col) = make_float2(o[nt][2] * i1, o[nt][3] * i1);
    }
}

// ---------------------------------------------------------------------------
// Residual + LayerNorm
// ---------------------------------------------------------------------------
__global__ __launch_bounds__(256)
void ln_kernel(const float* __restrict__ Oin, const float* __restrict__ X,
               const float* __restrict__ gamma, const float* __restrict__ beta,
               float* __restrict__ out)
{
    const int r = blockIdx.x;
    const int t = threadIdx.x;

    float4 o = reinterpret_cast<const float4*>(Oin + (size_t)r * DM)[t];
    float4 x = reinterpret_cast<const float4*>(X + (size_t)r * DM)[t];
    float v0 = o.x + x.x, v1 = o.y + x.y, v2 = o.z + x.z, v3 = o.w + x.w;

    float s1 = v0 + v1 + v2 + v3;
    float s2 = v0 * v0 + v1 * v1 + v2 * v2 + v3 * v3;
#pragma unroll
    for (int off = 16; off > 0; off >>= 1) {
        s1 += __shfl_xor_sync(0xffffffffu, s1, off);
        s2 += __shfl_xor_sync(0xffffffffu, s2, off);
    }

    __shared__ float rs1[8], rs2[8], stats[2];
    int warp = t >> 5, lane = t & 31;
    if (lane == 0) { rs1[warp] = s1; rs2[warp] = s2; }
    __syncthreads();
    if (t == 0) {
        float a = 0.0f, b2 = 0.0f;
#pragma unroll
        for (int wdx = 0; wdx < 8; ++wdx) { a += rs1[wdx]; b2 += rs2[wdx]; }
        float mean = a * (1.0f / 1024.0f);
        float var  = b2 * (1.0f / 1024.0f) - mean * mean;
        stats[0] = mean;
        stats[1] = rsqrtf(var + 1e-6f);
    }
    __syncthreads();
    float mean = stats[0], rstd = stats[1];

    float4 g  = reinterpret_cast<const float4*>(gamma)[t];
    float4 bb = reinterpret_cast<const float4*>(beta)[t];
    float4 y;
    y.x = (v0 - mean) * rstd * g.x + bb.x;
    y.y = (v1 - mean) * rstd * g.y + bb.y;
    y.z = (v2 - mean) * rstd * g.z + bb.z;
    y.w = (v3 - mean) * rstd * g.w + bb.w;
    reinterpret_cast<float4*>(out + (size_t)r * DM)[t] = y;
}

// ---------------------------------------------------------------------------
// Launcher
// ---------------------------------------------------------------------------
extern "C" void kernel_launch(void* const* d_in, const int* in_sizes, int n_in,
                              void* d_out, int out_size)
{
    const float* q     = (const float*)d_in[0];
    const float* k     = (const float*)d_in[1];
    const float* v     = (const float*)d_in[2];
    const float* Wq    = (const float*)d_in[3];
    const float* bq    = (const float*)d_in[4];
    const float* Wk    = (const float*)d_in[5];
    const float* bk    = (const float*)d_in[6];
    const float* Wv    = (const float*)d_in[7];
    const float* bv    = (const float*)d_in[8];
    const float* gamma = (const float*)d_in[9];
    const float* beta  = (const float*)d_in[10];
    float* out = (float*)d_out;

    __half *Qp, *Kp, *Vp, *WqT, *WkT, *WvT, *qh, *kh, *vh;
    float *Op;
    cudaGetSymbolAddress((void**)&Qp, g_Q);
    cudaGetSymbolAddress((void**)&Kp, g_K);
    cudaGetSymbolAddress((void**)&Vp, g_V);
    cudaGetSymbolAddress((void**)&Op, g_O);
    cudaGetSymbolAddress((void**)&WqT, g_WqT);
    cudaGetSymbolAddress((void**)&WkT, g_WkT);
    cudaGetSymbolAddress((void**)&WvT, g_WvT);
    cudaGetSymbolAddress((void**)&qh, g_qh);
    cudaGetSymbolAddress((void**)&kh, g_kh);
    cudaGetSymbolAddress((void**)&vh, g_vh);

    cudaFuncSetAttribute(gemm_h2, cudaFuncAttributeMaxDynamicSharedMemorySize,
                         GEMM_SMEM);
    cudaFuncSetAttribute(attn_h, cudaFuncAttributeMaxDynamicSharedMemorySize,
                         ATT_SMEM);

    // fp32 -> fp16 input copies (8M elements each => 2M float4 => 8192 blocks)
    f2h<<<8192, 256>>>((const float4*)q, (uint2*)qh);
    f2h<<<8192, 256>>>((const float4*)k, (uint2*)kh);
    f2h<<<8192, 256>>>((const float4*)v, (uint2*)vh);

    // W[k][n] -> W^T[n][k] (fp16)
    dim3 tb(32, 8), tg(32, 32);
    transpose_h<<<tg, tb>>>(Wq, WqT);
    transpose_h<<<tg, tb>>>(Wk, WkT);
    transpose_h<<<tg, tb>>>(Wv, WvT);

    dim3 ggrid(8, 64);
    gemm_h2<<<ggrid, 256, GEMM_SMEM>>>(qh, WqT, bq, Qp);
    gemm_h2<<<ggrid, 256, GEMM_SMEM>>>(kh, WkT, bk, Kp);
    gemm_h2<<<ggrid, 256, GEMM_SMEM>>>(vh, WvT, bv, Vp);

    attn_h<<<dim3(32, 32), 128, ATT_SMEM>>>(Qp, Kp, Vp, Op);

    ln_kernel<<<8192, 256>>>(Op, q, gamma, beta, out);
}

// round 11
// speedup vs baseline: 7.0722x; 1.0072x over previous
#include <cuda_runtime.h>
#include <cuda_fp16.h>
#include <cstdint>

#define S_LEN 2048
#define B_SZ  4
#define H_NUM 8
#define DKH   128
#define DM    1024

// Scratch (device globals — no allocations allowed)
__device__ __half g_Q[(size_t)B_SZ * H_NUM * S_LEN * DKH];  // [B,H,S,dk] fp16
__device__ __half g_K[(size_t)B_SZ * H_NUM * S_LEN * DKH];
__device__ __half g_V[(size_t)B_SZ * H_NUM * S_LEN * DKH];
__device__ float  g_O[(size_t)B_SZ * S_LEN * DM];           // [B,S,D] fp32
__device__ __half g_WqT[DM * DM];                           // W^T fp16: [n][k]
__device__ __half g_WkT[DM * DM];
__device__ __half g_WvT[DM * DM];
__device__ __half g_qh[(size_t)B_SZ * S_LEN * DM];          // fp16 copies of inputs
__device__ __half g_kh[(size_t)B_SZ * S_LEN * DM];
__device__ __half g_vh[(size_t)B_SZ * S_LEN * DM];

// ---------------------------------------------------------------------------
// helpers
// ---------------------------------------------------------------------------
__device__ __forceinline__ uint32_t pack2(float lo, float hi) {
    __half2 h = __float22half2_rn(make_float2(lo, hi));
    return *reinterpret_cast<uint32_t*>(&h);
}
__device__ __forceinline__ uint32_t smem_addr(const void* p) {
    return (uint32_t)__cvta_generic_to_shared(p);
}
__device__ __forceinline__ void cpa16(uint32_t dst, const void* src) {
    asm volatile("cp.async.cg.shared.global [%0], [%1], 16;" :: "r"(dst), "l"(src));
}
#define CP_COMMIT() asm volatile("cp.async.commit_group;" ::: "memory")
#define CP_WAIT(n)  asm volatile("cp.async.wait_group %0;" :: "n"(n) : "memory")

// D += A*B, m16n8k16 fp16 in / fp32 accum
__device__ __forceinline__ void mma16(float* d, const uint32_t* a, const uint32_t* b) {
    asm volatile(
        "mma.sync.aligned.m16n8k16.row.col.f32.f16.f16.f32 "
        "{%0,%1,%2,%3},{%4,%5,%6,%7},{%8,%9},{%0,%1,%2,%3};"
        : "+f"(d[0]), "+f"(d[1]), "+f"(d[2]), "+f"(d[3])
        : "r"(a[0]), "r"(a[1]), "r"(a[2]), "r"(a[3]), "r"(b[0]), "r"(b[1]));
}
#define LDSM4(r, addr)                                                        \
    asm volatile("ldmatrix.sync.aligned.m8n8.x4.shared.b16 {%0,%1,%2,%3},[%4];" \
        : "=r"((r)[0]), "=r"((r)[1]), "=r"((r)[2]), "=r"((r)[3]) : "r"(addr))
#define LDSM4T(r, addr)                                                       \
    asm volatile("ldmatrix.sync.aligned.m8n8.x4.trans.shared.b16 {%0,%1,%2,%3},[%4];" \
        : "=r"((r)[0]), "=r"((r)[1]), "=r"((r)[2]), "=r"((r)[3]) : "r"(addr))

// ---------------------------------------------------------------------------
// fp32 -> fp16 convert (each thread: 1 float4 -> 4 halves)
// ---------------------------------------------------------------------------
__global__ __launch_bounds__(256)
void f2h(const float4* __restrict__ in, uint2* __restrict__ out)
{
    size_t i = (size_t)blockIdx.x * 256 + threadIdx.x;
    float4 v = in[i];
    uint2 u;
    u.x = pack2(v.x, v.y);
    u.y = pack2(v.z, v.w);
    out[i] = u;
}

// ---------------------------------------------------------------------------
// Tiled transpose + fp16 convert: out[n][k] = half(in[k][n])
// ---------------------------------------------------------------------------
__global__ __launch_bounds__(256)
void transpose_h(const float* __restrict__ in, __half* __restrict__ out)
{
    __shared__ float t[32][33];
    int x  = blockIdx.x * 32 + threadIdx.x;
    int y0 = blockIdx.y * 32;
#pragma unroll
    for (int j = threadIdx.y; j < 32; j += 8)
        t[j][threadIdx.x] = in[(size_t)(y0 + j) * DM + x];
    __syncthreads();
    int x2 = blockIdx.y * 32 + threadIdx.x;
#pragma unroll
    for (int j = threadIdx.y; j < 32; j += 8)
        out[(size_t)(blockIdx.x * 32 + j) * DM + x2] = __float2half(t[threadIdx.x][j]);
}

// ---------------------------------------------------------------------------
// fp16 mma GEMM, 4-stage cp.async pipeline, single barrier per iter.
// Y = Xh @ W + b. M=8192 N=1024 K=1024. CTA 128x128, BK=32, 8 warps.
// smem row stride 40 halves (80 B): ldmatrix phases conflict-free.
// ---------------------------------------------------------------------------
#define GROWB  80                         // bytes per smem row
#define AMAT_B (128 * GROWB)              // 10240 bytes per matrix
#define STAGE_B (2 * AMAT_B)              // 20480 per stage
#define GEMM_SMEM (4 * STAGE_B)           // 81920 bytes

__global__ __launch_bounds__(256)
void gemm_h2(const __half* __restrict__ Xh, const __half* __restrict__ Wt,
             const float* __restrict__ bias, __half* __restrict__ out)
{
    extern __shared__ __align__(16) char sm_raw[];
    const uint32_t sb = smem_addr(sm_raw);
    const int tid  = threadIdx.x;
    const int wid  = tid >> 5, lane = tid & 31;
    const int grp  = lane >> 2, kq = lane & 3;
    const int wm   = (wid >> 2) * 64, wn = (wid & 3) * 32;
    const int n0   = blockIdx.x * 128;   // h = blockIdx.x
    const int m0   = blockIdx.y * 128;

    float acc[4][4][4];
#pragma unroll
    for (int mt = 0; mt < 4; ++mt)
#pragma unroll
        for (int nt = 0; nt < 4; ++nt)
#pragma unroll
            for (int e = 0; e < 4; ++e) acc[mt][nt][e] = 0.0f;

    // cp.async tile loader: 512 16B chunks per matrix, 2 per thread
    auto load_stage = [&](int st, int kt) {
        const uint32_t base = sb + st * STAGE_B;
        const __half* Ag = Xh + (size_t)m0 * 1024 + kt * 32;
        const __half* Bg = Wt + (size_t)n0 * 1024 + kt * 32;
#pragma unroll
        for (int t = 0; t < 2; ++t) {
            int idx = tid + t * 256;          // 0..511
            int r = idx >> 2, c = idx & 3;
            cpa16(base + r * GROWB + c * 16,          Ag + (size_t)r * 1024 + c * 8);
            cpa16(base + AMAT_B + r * GROWB + c * 16, Bg + (size_t)r * 1024 + c * 8);
        }
    };

    // ldmatrix per-lane addressing
    const int arow = wm + ((lane >> 3) & 1) * 8 + (lane & 7);
    const int acol = (lane >> 4) * 8;                  // halves
    const int brow = wn + ((lane >> 4) & 1) * 8 + (lane & 7);
    const int bcol = ((lane >> 3) & 1) * 8;

    load_stage(0, 0); CP_COMMIT();
    load_stage(1, 1); CP_COMMIT();
    load_stage(2, 2); CP_COMMIT();

    for (int i = 0; i < 32; ++i) {
        CP_WAIT(2);
        __syncthreads();

        // refill stage freed last iteration ((i+3)&3 == (i-1)&3)
        if (i + 3 < 32) load_stage((i + 3) & 3, i + 3);
        CP_COMMIT();   // always commit to keep group accounting uniform

        const uint32_t Ac = sb + (i & 3) * STAGE_B;
        const uint32_t Bc = Ac + AMAT_B;
#pragma unroll
        for (int ks = 0; ks < 2; ++ks) {
            uint32_t a[4][4], b[2][4];
#pragma unroll
            for (int mt = 0; mt < 4; ++mt)
                LDSM4(a[mt], Ac + (arow + mt * 16) * GROWB + (ks * 16 + acol) * 2);
#pragma unroll
            for (int ntp = 0; ntp < 2; ++ntp)
                LDSM4(b[ntp], Bc + (brow + ntp * 16) * GROWB + (ks * 16 + bcol) * 2);
#pragma unroll
            for (int mt = 0; mt < 4; ++mt) {
                mma16(acc[mt][0], a[mt], &b[0][0]);
                mma16(acc[mt][1], a[mt], &b[0][2]);
                mma16(acc[mt][2], a[mt], &b[1][0]);
                mma16(acc[mt][3], a[mt], &b[1][2]);
            }
        }
    }

    // epilogue: bias + fp16 head-split store ([B,H,S,dk])
    const int h = blockIdx.x;
#pragma unroll
    for (int mt = 0; mt < 4; ++mt) {
#pragma unroll
        for (int half_ = 0; half_ < 2; ++half_) {
            int m = m0 + wm + mt * 16 + grp + half_ * 8;
            int b = m >> 11, s = m & 2047;
            __half* orow = out + (((size_t)b * H_NUM + h) * S_LEN + s) * DKH;
#pragma unroll
            for (int nt = 0; nt < 4; ++nt) {
                int nl = wn + nt * 8 + 2 * kq;
                float2 bv = *reinterpret_cast<const float2*>(bias + n0 + nl);
                uint32_t u = pack2(acc[mt][nt][half_ * 2 + 0] + bv.x,
                                   acc[mt][nt][half_ * 2 + 1] + bv.y);
                *reinterpret_cast<uint32_t*>(orow + nl) = u;
            }
        }
    }
}

// ---------------------------------------------------------------------------
// Flash attention, fp16 mma, double-buffered K/V cp.async pipeline.
// BQ=64, BKV=64, dk=128, 4 warps. One barrier per kv iteration.
// ---------------------------------------------------------------------------
#define KST2 136
#define VST2 136
#define PST2 72
#define KV_K_B  (64 * KST2 * 2)              // 17408 bytes (K region)
#define KV_ST_B (2 * KV_K_B)                 // 34816 bytes per stage (K+V)
#define ATT_P_OFF (2 * KV_ST_B)              // 69632
#define ATT_SMEM (ATT_P_OFF + 4 * 16 * PST2 * 2)  // 78848 bytes

__global__ __launch_bounds__(128)
void attn_h(const __half* __restrict__ Q, const __half* __restrict__ K,
            const __half* __restrict__ V, float* __restrict__ O)
{
    extern __shared__ __align__(16) char sm_raw[];
    const uint32_t sb = smem_addr(sm_raw);
    __half* Ps = reinterpret_cast<__half*>(sm_raw + ATT_P_OFF);

    const int qt  = (int)gridDim.x - 1 - (int)blockIdx.x;  // heavy tiles first
    const int bh  = blockIdx.y;
    const int tid = threadIdx.x;
    const int w   = tid >> 5, lane = tid & 31;
    const int grp = lane >> 2, kq = lane & 3;

    const __half* Qg = Q + ((size_t)bh * S_LEN + (size_t)qt * 64) * DKH;
    const __half* Kg = K + (size_t)bh * S_LEN * DKH;
    const __half* Vg = V + (size_t)bh * S_LEN * DKH;

    // kv tile loader into stage st (K + V), 8 chunks per thread each
    auto load_kv = [&](int st, int kt) {
        const uint32_t kb = sb + st * KV_ST_B;
        const uint32_t vb = kb + KV_K_B;
        const __half* Kt = Kg + (size_t)kt * 64 * DKH;
        const __half* Vt = Vg + (size_t)kt * 64 * DKH;
#pragma unroll
        for (int j = 0; j < 8; ++j) {
            int idx = tid + j * 128;
            int r = idx >> 4, c = idx & 15;
            cpa16(kb + r * (KST2 * 2) + c * 16, Kt + (size_t)r * DKH + c * 8);
            cpa16(vb + r * (VST2 * 2) + c * 16, Vt + (size_t)r * DKH + c * 8);
        }
    };

    // ---- stage Q (into stage-1 K region) and kv tile 0 concurrently ----
    {
        const uint32_t qb = sb + KV_ST_B;   // stage 1 K region
        // FIX (R9 NaN): full Q tile is 64 rows x 16 chunks = 1024 chunks.
#pragma unroll
        for (int j = 0; j < 8; ++j) {
            int idx = tid + j * 128;
            int r = idx >> 4, c = idx & 15;
            cpa16(qb + r * (KST2 * 2) + c * 16, Qg + (size_t)r * DKH + c * 8);
        }
        CP_COMMIT();
        load_kv(0, 0);
        CP_COMMIT();
    }
    CP_WAIT(1);        // Q ready (kv0 may still be in flight)
    __syncthreads();

    // ---- extract Q A-fragments ----
    uint32_t qa[8][4];
    {
        const int qrow = w * 16 + ((lane >> 3) & 1) * 8 + (lane & 7);
        const int qcol = (lane >> 4) * 8;
        const uint32_t qb = sb + KV_ST_B;
#pragma unroll
        for (int ks = 0; ks < 8; ++ks)
            LDSM4(qa[ks], qb + (qrow * KST2 + ks * 16 + qcol) * 2);
    }

    float o[16][4];
#pragma unroll
    for (int nt = 0; nt < 16; ++nt)
#pragma unroll
        for (int e = 0; e < 4; ++e) o[nt][e] = 0.0f;
    float m0 = -1e30f, m1 = -1e30f, l0 = 0.0f, l1 = 0.0f;

    const float sc = 0.08838834764831843f;  // 1/sqrt(128)
    const int rowlo = w * 16 + grp;
    const int rowhi = rowlo + 8;

    // ldmatrix lane addressing (per iter)
    const int krow_l = ((lane >> 4) & 1) * 8 + (lane & 7);   // K B-frag rows
    const int kcol_l = ((lane >> 3) & 1) * 8;
    const int prow_l = ((lane >> 3) & 1) * 8 + (lane & 7);   // P A-frag rows
    const int pcol_l = (lane >> 4) * 8;
    const int lrow   = ((lane >> 3) & 1) * 8 + (lane & 7);   // V trans rows
    const int lcol   = (lane >> 4) * 8;

    for (int kt = 0; kt <= qt; ++kt) {
        CP_WAIT(0);        // kv tile kt resident
        __syncthreads();   // all warps past last iter's compute + this wait

        // prefetch next kv tile into the other stage (overwrites oldest/Q)
        if (kt + 1 <= qt) load_kv((kt + 1) & 1, kt + 1);
        CP_COMMIT();       // always commit (uniform group accounting)

        const uint32_t Kst = sb + (kt & 1) * KV_ST_B;
        const uint32_t Vst = Kst + KV_K_B;

        // ---- S = Q @ K^T : 8 k16-steps x 4 nt-pairs (ldmatrix.x4) ----
        float sfr[8][4];
#pragma unroll
        for (int nt = 0; nt < 8; ++nt)
#pragma unroll
            for (int e = 0; e < 4; ++e) sfr[nt][e] = 0.0f;

#pragma unroll
        for (int ks = 0; ks < 8; ++ks) {
#pragma unroll
            for (int ntp = 0; ntp < 4; ++ntp) {
                uint32_t bb[4];
                LDSM4(bb, Kst + ((ntp * 16 + krow_l) * KST2 + ks * 16 + kcol_l) * 2);
                mma16(sfr[2 * ntp + 0], qa[ks], &bb[0]);
                mma16(sfr[2 * ntp + 1], qa[ks], &bb[2]);
            }
        }

        // scale + causal mask on diagonal tile
#pragma unroll
        for (int nt = 0; nt < 8; ++nt) {
#pragma unroll
            for (int e = 0; e < 4; ++e) sfr[nt][e] *= sc;
            if (kt == qt) {
                int col = nt * 8 + 2 * kq;
                if (col + 0 > rowlo) sfr[nt][0] = -1e9f;
                if (col + 1 > rowlo) sfr[nt][1] = -1e9f;
                if (col + 0 > rowhi) sfr[nt][2] = -1e9f;
                if (col + 1 > rowhi) sfr[nt][3] = -1e9f;
            }
        }

        // ---- online softmax ----
        float mx0 = -1e30f, mx1 = -1e30f;
#pragma unroll
        for (int nt = 0; nt < 8; ++nt) {
            mx0 = fmaxf(mx0, fmaxf(sfr[nt][0], sfr[nt][1]));
            mx1 = fmaxf(mx1, fmaxf(sfr[nt][2], sfr[nt][3]));
        }
        mx0 = fmaxf(mx0, __shfl_xor_sync(0xffffffffu, mx0, 1));
        mx0 = fmaxf(mx0, __shfl_xor_sync(0xffffffffu, mx0, 2));
        mx1 = fmaxf(mx1, __shfl_xor_sync(0xffffffffu, mx1, 1));
        mx1 = fmaxf(mx1, __shfl_xor_sync(0xffffffffu, mx1, 2));

        float mn0 = fmaxf(m0, mx0), mn1 = fmaxf(m1, mx1);
        float c0 = __expf(m0 - mn0), c1 = __expf(m1 - mn1);
        m0 = mn0; m1 = mn1;

        float s0 = 0.0f, s1 = 0.0f;
#pragma unroll
        for (int nt = 0; nt < 8; ++nt) {
            sfr[nt][0] = __expf(sfr[nt][0] - m0);
            sfr[nt][1] = __expf(sfr[nt][1] - m0);
            sfr[nt][2] = __expf(sfr[nt][2] - m1);
            sfr[nt][3] = __expf(sfr[nt][3] - m1);
            s0 += sfr[nt][0] + sfr[nt][1];
            s1 += sfr[nt][2] + sfr[nt][3];
        }
        s0 += __shfl_xor_sync(0xffffffffu, s0, 1);
        s0 += __shfl_xor_sync(0xffffffffu, s0, 2);
        s1 += __shfl_xor_sync(0xffffffffu, s1, 1);
        s1 += __shfl_xor_sync(0xffffffffu, s1, 2);
        l0 = l0 * c0 + s0;
        l1 = l1 * c1 + s1;

#pragma unroll
        for (int nt = 0; nt < 16; ++nt) {
            o[nt][0] *= c0; o[nt][1] *= c0;
            o[nt][2] *= c1; o[nt][3] *= c1;
        }

        // ---- P (fp16) to warp-private smem ----
        __half* Pw = Ps + w * (16 * PST2);
        const uint32_t Pwb = smem_addr(Pw);
#pragma unroll
        for (int nt = 0; nt < 8; ++nt) {
            int col = nt * 8 + 2 * kq;
            *reinterpret_cast<uint32_t*>(Pw + grp * PST2 + col) =
                pack2(sfr[nt][0], sfr[nt][1]);
            *reinterpret_cast<uint32_t*>(Pw + (grp + 8) * PST2 + col) =
                pack2(sfr[nt][2], sfr[nt][3]);
        }
        __syncwarp();

        // ---- O += P @ V : 4 k16-steps; P via ldmatrix, V via ldmatrix.trans ----
#pragma unroll
        for (int ks = 0; ks < 4; ++ks) {
            uint32_t a[4];
            LDSM4(a, Pwb + (prow_l * PST2 + ks * 16 + pcol_l) * 2);
            const uint32_t vbase = Vst + ((ks * 16 + lrow) * VST2 + lcol) * 2;
#pragma unroll
            for (int ntp = 0; ntp < 8; ++ntp) {
                uint32_t bb[4];
                LDSM4T(bb, vbase + ntp * 32);
                mma16(o[2 * ntp + 0], a, &bb[0]);
                mma16(o[2 * ntp + 1], a, &bb[2]);
            }
        }
        __syncwarp();
    }

    // ---- epilogue: normalize, write fp32 [B,S,D] ----
    const int b = bh >> 3, h = bh & 7;
    float i0 = 1.0f / l0, i1 = 1.0f / l1;
    int q0 = qt * 64 + rowlo;
    float* r0 = O + ((size_t)b * S_LEN + q0) * DM + h * DKH;
    float* r1 = O + ((size_t)b * S_LEN + q0 + 8) * DM + h * DKH;
#pragma unroll
    for (int nt = 0; nt < 16; ++nt) {
        int col = nt * 8 + 2 * kq;
        *reinterpret_cast<float2*>(r0 + col) = make_float2(o[nt][0] * i0, o[nt][1] * i0);
        *reinterpret_cast<float2*>(r1 + col) = make_float2(o[nt][2] * i1, o[nt][3] * i1);
    }
}

// ---------------------------------------------------------------------------
// Residual + LayerNorm
// ---------------------------------------------------------------------------
__global__ __launch_bounds__(256)
void ln_kernel(const float* __restrict__ Oin, const float* __restrict__ X,
               const float* __restrict__ gamma, const float* __restrict__ beta,
               float* __restrict__ out)
{
    const int r = blockIdx.x;
    const int t = threadIdx.x;

    float4 o = reinterpret_cast<const float4*>(Oin + (size_t)r * DM)[t];
    float4 x = reinterpret_cast<const float4*>(X + (size_t)r * DM)[t];
    float v0 = o.x + x.x, v1 = o.y + x.y, v2 = o.z + x.z, v3 = o.w + x.w;

    float s1 = v0 + v1 + v2 + v3;
    float s2 = v0 * v0 + v1 * v1 + v2 * v2 + v3 * v3;
#pragma unroll
    for (int off = 16; off > 0; off >>= 1) {
        s1 += __shfl_xor_sync(0xffffffffu, s1, off);
        s2 += __shfl_xor_sync(0xffffffffu, s2, off);
    }

    __shared__ float rs1[8], rs2[8], stats[2];
    int warp = t >> 5, lane = t & 31;
    if (lane == 0) { rs1[warp] = s1; rs2[warp] = s2; }
    __syncthreads();
    if (t == 0) {
        float a = 0.0f, b2 = 0.0f;
#pragma unroll
        for (int wdx = 0; wdx < 8; ++wdx) { a += rs1[wdx]; b2 += rs2[wdx]; }
        float mean = a * (1.0f / 1024.0f);
        float var  = b2 * (1.0f / 1024.0f) - mean * mean;
        stats[0] = mean;
        stats[1] = rsqrtf(var + 1e-6f);
    }
    __syncthreads();
    float mean = stats[0], rstd = stats[1];

    float4 g  = reinterpret_cast<const float4*>(gamma)[t];
    float4 bb = reinterpret_cast<const float4*>(beta)[t];
    float4 y;
    y.x = (v0 - mean) * rstd * g.x + bb.x;
    y.y = (v1 - mean) * rstd * g.y + bb.y;
    y.z = (v2 - mean) * rstd * g.z + bb.z;
    y.w = (v3 - mean) * rstd * g.w + bb.w;
    reinterpret_cast<float4*>(out + (size_t)r * DM)[t] = y;
}

// ---------------------------------------------------------------------------
// Launcher
// ---------------------------------------------------------------------------
extern "C" void kernel_launch(void* const* d_in, const int* in_sizes, int n_in,
                              void* d_out, int out_size)
{
    const float* q     = (const float*)d_in[0];
    const float* k     = (const float*)d_in[1];
    const float* v     = (const float*)d_in[2];
    const float* Wq    = (const float*)d_in[3];
    const float* bq    = (const float*)d_in[4];
    const float* Wk    = (const float*)d_in[5];
    const float* bk    = (const float*)d_in[6];
    const float* Wv    = (const float*)d_in[7];
    const float* bv    = (const float*)d_in[8];
    const float* gamma = (const float*)d_in[9];
    const float* beta  = (const float*)d_in[10];
    float* out = (float*)d_out;

    __half *Qp, *Kp, *Vp, *WqT, *WkT, *WvT, *qh, *kh, *vh;
    float *Op;
    cudaGetSymbolAddress((void**)&Qp, g_Q);
    cudaGetSymbolAddress((void**)&Kp, g_K);
    cudaGetSymbolAddress((void**)&Vp, g_V);
    cudaGetSymbolAddress((void**)&Op, g_O);
    cudaGetSymbolAddress((void**)&WqT, g_WqT);
    cudaGetSymbolAddress((void**)&WkT, g_WkT);
    cudaGetSymbolAddress((void**)&WvT, g_WvT);
    cudaGetSymbolAddress((void**)&qh, g_qh);
    cudaGetSymbolAddress((void**)&kh, g_kh);
    cudaGetSymbolAddress((void**)&vh, g_vh);

    cudaFuncSetAttribute(gemm_h2, cudaFuncAttributeMaxDynamicSharedMemorySize,
                         GEMM_SMEM);
    cudaFuncSetAttribute(attn_h, cudaFuncAttributeMaxDynamicSharedMemorySize,
                         ATT_SMEM);

    // fp32 -> fp16 input copies
    f2h<<<8192, 256>>>((const float4*)q, (uint2*)qh);
    f2h<<<8192, 256>>>((const float4*)k, (uint2*)kh);
    f2h<<<8192, 256>>>((const float4*)v, (uint2*)vh);

    // W[k][n] -> W^T[n][k] (fp16)
    dim3 tb(32, 8), tg(32, 32);
    transpose_h<<<tg, tb>>>(Wq, WqT);
    transpose_h<<<tg, tb>>>(Wk, WkT);
    transpose_h<<<tg, tb>>>(Wv, WvT);

    dim3 ggrid(8, 64);
    gemm_h2<<<ggrid, 256, GEMM_SMEM>>>(qh, WqT, bq, Qp);
    gemm_h2<<<ggrid, 256, GEMM_SMEM>>>(kh, WkT, bk, Kp);
    gemm_h2<<<ggrid, 256, GEMM_SMEM>>>(vh, WvT, bv, Vp);

    attn_h<<<dim3(32, 32), 128, ATT_SMEM>>>(Qp, Kp, Vp, Op);

    ln_kernel<<<8192, 256>>>(Op, q, gamma, beta, out);
}

// round 12
// speedup vs baseline: 7.3192x; 1.0349x over previous
#include <cuda_runtime.h>
#include <cuda_fp16.h>
#include <cstdint>

#define S_LEN 2048
#define B_SZ  4
#define H_NUM 8
#define DKH   128
#define DM    1024

// Scratch (device globals — no allocations allowed)
__device__ __half g_Q[(size_t)B_SZ * H_NUM * S_LEN * DKH];  // [B,H,S,dk] fp16
__device__ __half g_K[(size_t)B_SZ * H_NUM * S_LEN * DKH];
__device__ __half g_V[(size_t)B_SZ * H_NUM * S_LEN * DKH];
__device__ float  g_O[(size_t)B_SZ * S_LEN * DM];           // [B,S,D] fp32
__device__ __half g_WqT[DM * DM];                           // W^T fp16: [n][k]
__device__ __half g_WkT[DM * DM];
__device__ __half g_WvT[DM * DM];
__device__ __half g_qh[(size_t)B_SZ * S_LEN * DM];          // fp16 copies of inputs
__device__ __half g_kh[(size_t)B_SZ * S_LEN * DM];
__device__ __half g_vh[(size_t)B_SZ * S_LEN * DM];

// ---------------------------------------------------------------------------
// helpers
// ---------------------------------------------------------------------------
__device__ __forceinline__ uint32_t pack2(float lo, float hi) {
    __half2 h = __float22half2_rn(make_float2(lo, hi));
    return *reinterpret_cast<uint32_t*>(&h);
}
__device__ __forceinline__ uint32_t smem_addr(const void* p) {
    return (uint32_t)__cvta_generic_to_shared(p);
}
__device__ __forceinline__ void cpa16(uint32_t dst, const void* src) {
    asm volatile("cp.async.cg.shared.global [%0], [%1], 16;" :: "r"(dst), "l"(src));
}
#define CP_COMMIT() asm volatile("cp.async.commit_group;" ::: "memory")
#define CP_WAIT(n)  asm volatile("cp.async.wait_group %0;" :: "n"(n) : "memory")

// D += A*B, m16n8k16 fp16 in / fp32 accum
__device__ __forceinline__ void mma16(float* d, const uint32_t* a, const uint32_t* b) {
    asm volatile(
        "mma.sync.aligned.m16n8k16.row.col.f32.f16.f16.f32 "
        "{%0,%1,%2,%3},{%4,%5,%6,%7},{%8,%9},{%0,%1,%2,%3};"
        : "+f"(d[0]), "+f"(d[1]), "+f"(d[2]), "+f"(d[3])
        : "r"(a[0]), "r"(a[1]), "r"(a[2]), "r"(a[3]), "r"(b[0]), "r"(b[1]));
}
#define LDSM4(r, addr)                                                        \
    asm volatile("ldmatrix.sync.aligned.m8n8.x4.shared.b16 {%0,%1,%2,%3},[%4];" \
        : "=r"((r)[0]), "=r"((r)[1]), "=r"((r)[2]), "=r"((r)[3]) : "r"(addr))
#define LDSM4T(r, addr)                                                       \
    asm volatile("ldmatrix.sync.aligned.m8n8.x4.trans.shared.b16 {%0,%1,%2,%3},[%4];" \
        : "=r"((r)[0]), "=r"((r)[1]), "=r"((r)[2]), "=r"((r)[3]) : "r"(addr))

// ---------------------------------------------------------------------------
// fp32 -> fp16 convert (each thread: 1 float4 -> 4 halves)
// ---------------------------------------------------------------------------
__global__ __launch_bounds__(256)
void f2h(const float4* __restrict__ in, uint2* __restrict__ out)
{
    size_t i = (size_t)blockIdx.x * 256 + threadIdx.x;
    float4 v = in[i];
    uint2 u;
    u.x = pack2(v.x, v.y);
    u.y = pack2(v.z, v.w);
    out[i] = u;
}

// ---------------------------------------------------------------------------
// Fused tiled transpose + fp16 convert for 3 weights: out[n][k] = half(in[k][n])
// ---------------------------------------------------------------------------
__global__ __launch_bounds__(256)
void transpose_h3(const float* __restrict__ w0, const float* __restrict__ w1,
                  const float* __restrict__ w2, __half* __restrict__ o0,
                  __half* __restrict__ o1, __half* __restrict__ o2)
{
    const int z = blockIdx.z;
    const float* in  = (z == 0) ? w0 : (z == 1) ? w1 : w2;
    __half*      out = (z == 0) ? o0 : (z == 1) ? o1 : o2;

    __shared__ float t[32][33];
    int x  = blockIdx.x * 32 + threadIdx.x;
    int y0 = blockIdx.y * 32;
#pragma unroll
    for (int j = threadIdx.y; j < 32; j += 8)
        t[j][threadIdx.x] = in[(size_t)(y0 + j) * DM + x];
    __syncthreads();
    int x2 = blockIdx.y * 32 + threadIdx.x;
#pragma unroll
    for (int j = threadIdx.y; j < 32; j += 8)
        out[(size_t)(blockIdx.x * 32 + j) * DM + x2] = __float2half(t[threadIdx.x][j]);
}

// ---------------------------------------------------------------------------
// Fused fp16 mma GEMM (3 projections via blockIdx.z), 4-stage cp.async
// pipeline, single barrier per iter. Y = Xh @ W + b. M=8192 N=1024 K=1024.
// CTA 128x128, BK=32, 8 warps. smem row stride 40 halves: conflict-free.
// ---------------------------------------------------------------------------
#define GROWB  80                         // bytes per smem row
#define AMAT_B (128 * GROWB)              // 10240 bytes per matrix
#define STAGE_B (2 * AMAT_B)              // 20480 per stage
#define GEMM_SMEM (4 * STAGE_B)           // 81920 bytes

__global__ __launch_bounds__(256)
void gemm_h3(const __half* __restrict__ X0, const __half* __restrict__ X1,
             const __half* __restrict__ X2, const __half* __restrict__ W0,
             const __half* __restrict__ W1, const __half* __restrict__ W2,
             const float* __restrict__ b0, const float* __restrict__ b1,
             const float* __restrict__ b2, __half* __restrict__ o0,
             __half* __restrict__ o1, __half* __restrict__ o2)
{
    const int z = blockIdx.z;
    const __half* Xh   = (z == 0) ? X0 : (z == 1) ? X1 : X2;
    const __half* Wt   = (z == 0) ? W0 : (z == 1) ? W1 : W2;
    const float*  bias = (z == 0) ? b0 : (z == 1) ? b1 : b2;
    __half*       out  = (z == 0) ? o0 : (z == 1) ? o1 : o2;

    extern __shared__ __align__(16) char sm_raw[];
    const uint32_t sb = smem_addr(sm_raw);
    const int tid  = threadIdx.x;
    const int wid  = tid >> 5, lane = tid & 31;
    const int grp  = lane >> 2, kq = lane & 3;
    const int wm   = (wid >> 2) * 64, wn = (wid & 3) * 32;
    const int n0   = blockIdx.x * 128;   // h = blockIdx.x
    const int m0   = blockIdx.y * 128;

    float acc[4][4][4];
#pragma unroll
    for (int mt = 0; mt < 4; ++mt)
#pragma unroll
        for (int nt = 0; nt < 4; ++nt)
#pragma unroll
            for (int e = 0; e < 4; ++e) acc[mt][nt][e] = 0.0f;

    // cp.async tile loader: 512 16B chunks per matrix, 2 per thread
    auto load_stage = [&](int st, int kt) {
        const uint32_t base = sb + st * STAGE_B;
        const __half* Ag = Xh + (size_t)m0 * 1024 + kt * 32;
        const __half* Bg = Wt + (size_t)n0 * 1024 + kt * 32;
#pragma unroll
        for (int t = 0; t < 2; ++t) {
            int idx = tid + t * 256;          // 0..511
            int r = idx >> 2, c = idx & 3;
            cpa16(base + r * GROWB + c * 16,          Ag + (size_t)r * 1024 + c * 8);
            cpa16(base + AMAT_B + r * GROWB + c * 16, Bg + (size_t)r * 1024 + c * 8);
        }
    };

    // ldmatrix per-lane addressing
    const int arow = wm + ((lane >> 3) & 1) * 8 + (lane & 7);
    const int acol = (lane >> 4) * 8;                  // halves
    const int brow = wn + ((lane >> 4) & 1) * 8 + (lane & 7);
    const int bcol = ((lane >> 3) & 1) * 8;

    load_stage(0, 0); CP_COMMIT();
    load_stage(1, 1); CP_COMMIT();
    load_stage(2, 2); CP_COMMIT();

    for (int i = 0; i < 32; ++i) {
        CP_WAIT(2);
        __syncthreads();

        // refill stage freed last iteration ((i+3)&3 == (i-1)&3)
        if (i + 3 < 32) load_stage((i + 3) & 3, i + 3);
        CP_COMMIT();   // always commit to keep group accounting uniform

        const uint32_t Ac = sb + (i & 3) * STAGE_B;
        const uint32_t Bc = Ac + AMAT_B;
#pragma unroll
        for (int ks = 0; ks < 2; ++ks) {
            uint32_t a[4][4], b[2][4];
#pragma unroll
            for (int mt = 0; mt < 4; ++mt)
                LDSM4(a[mt], Ac + (arow + mt * 16) * GROWB + (ks * 16 + acol) * 2);
#pragma unroll
            for (int ntp = 0; ntp < 2; ++ntp)
                LDSM4(b[ntp], Bc + (brow + ntp * 16) * GROWB + (ks * 16 + bcol) * 2);
#pragma unroll
            for (int mt = 0; mt < 4; ++mt) {
                mma16(acc[mt][0], a[mt], &b[0][0]);
                mma16(acc[mt][1], a[mt], &b[0][2]);
                mma16(acc[mt][2], a[mt], &b[1][0]);
                mma16(acc[mt][3], a[mt], &b[1][2]);
            }
        }
    }

    // epilogue: bias + fp16 head-split store ([B,H,S,dk])
    const int h = blockIdx.x;
#pragma unroll
    for (int mt = 0; mt < 4; ++mt) {
#pragma unroll
        for (int half_ = 0; half_ < 2; ++half_) {
            int m = m0 + wm + mt * 16 + grp + half_ * 8;
            int b = m >> 11, s = m & 2047;
            __half* orow = out + (((size_t)b * H_NUM + h) * S_LEN + s) * DKH;
#pragma unroll
            for (int nt = 0; nt < 4; ++nt) {
                int nl = wn + nt * 8 + 2 * kq;
                float2 bv = *reinterpret_cast<const float2*>(bias + n0 + nl);
                uint32_t u = pack2(acc[mt][nt][half_ * 2 + 0] + bv.x,
                                   acc[mt][nt][half_ * 2 + 1] + bv.y);
                *reinterpret_cast<uint32_t*>(orow + nl) = u;
            }
        }
    }
}

// ---------------------------------------------------------------------------
// Flash attention, fp16 mma, BQ=128 (8 warps), BKV=64, dk=128.
// Double-buffered K/V cp.async; each K/V tile serves 128 Q rows.
// ---------------------------------------------------------------------------
#define KST2 136
#define VST2 136
#define PST2 72
#define KV_K_B  (64 * KST2 * 2)              // 17408 bytes (K region)
#define KV_ST_B (2 * KV_K_B)                 // 34816 bytes per stage (K+V)
#define ATT_P_OFF (2 * KV_ST_B)              // 69632
#define ATT_SMEM (ATT_P_OFF + 8 * 16 * PST2 * 2)  // 88064 bytes

__global__ __launch_bounds__(256, 1)
void attn_h(const __half* __restrict__ Q, const __half* __restrict__ K,
            const __half* __restrict__ V, float* __restrict__ O)
{
    extern __shared__ __align__(16) char sm_raw[];
    const uint32_t sb = smem_addr(sm_raw);
    __half* Ps = reinterpret_cast<__half*>(sm_raw + ATT_P_OFF);

    const int qt  = (int)gridDim.x - 1 - (int)blockIdx.x;  // heavy tiles first
    const int bh  = blockIdx.y;
    const int tid = threadIdx.x;
    const int w   = tid >> 5, lane = tid & 31;
    const int grp = lane >> 2, kq = lane & 3;
    const int nkv = 2 * qt + 2;              // kv tiles (BKV=64) for BQ=128

    const __half* Qg = Q + ((size_t)bh * S_LEN + (size_t)qt * 128) * DKH;
    const __half* Kg = K + (size_t)bh * S_LEN * DKH;
    const __half* Vg = V + (size_t)bh * S_LEN * DKH;

    // kv tile loader into stage st (K + V), 1024 chunks over 256 threads
    auto load_kv = [&](int st, int kt) {
        const uint32_t kb = sb + st * KV_ST_B;
        const uint32_t vb = kb + KV_K_B;
        const __half* Kt = Kg + (size_t)kt * 64 * DKH;
        const __half* Vt = Vg + (size_t)kt * 64 * DKH;
#pragma unroll
        for (int j = 0; j < 4; ++j) {
            int idx = tid + j * 256;
            int r = idx >> 4, c = idx & 15;
            cpa16(kb + r * (KST2 * 2) + c * 16, Kt + (size_t)r * DKH + c * 8);
            cpa16(vb + r * (VST2 * 2) + c * 16, Vt + (size_t)r * DKH + c * 8);
        }
    };

    // ---- stage Q (128 rows x 128 cols = 2048 chunks) into stage-1 K+V
    // regions (contiguous: row r at qb + r*272 for r in 0..127), plus kv0 ----
    {
        const uint32_t qb = sb + KV_ST_B;   // stage 1 base
#pragma unroll
        for (int j = 0; j < 8; ++j) {
            int idx = tid + j * 256;
            int r = idx >> 4, c = idx & 15;
            cpa16(qb + r * (KST2 * 2) + c * 16, Qg + (size_t)r * DKH + c * 8);
        }
        CP_COMMIT();
        load_kv(0, 0);
        CP_COMMIT();
    }
    CP_WAIT(1);        // Q ready (kv0 may still be in flight)
    __syncthreads();

    // ---- extract Q A-fragments (warp w owns rows w*16..w*16+15) ----
    uint32_t qa[8][4];
    {
        const int qrow = w * 16 + ((lane >> 3) & 1) * 8 + (lane & 7);
        const int qcol = (lane >> 4) * 8;
        const uint32_t qb = sb + KV_ST_B;
#pragma unroll
        for (int ks = 0; ks < 8; ++ks)
            LDSM4(qa[ks], qb + (qrow * KST2 + ks * 16 + qcol) * 2);
    }

    float o[16][4];
#pragma unroll
    for (int nt = 0; nt < 16; ++nt)
#pragma unroll
        for (int e = 0; e < 4; ++e) o[nt][e] = 0.0f;
    float m0 = -1e30f, m1 = -1e30f, l0 = 0.0f, l1 = 0.0f;

    const float sc = 0.08838834764831843f;  // 1/sqrt(128)
    const int rowlo = w * 16 + grp;          // tile-local Q row (0..127)
    const int rowhi = rowlo + 8;

    // ldmatrix lane addressing (per iter)
    const int krow_l = ((lane >> 4) & 1) * 8 + (lane & 7);   // K B-frag rows
    const int kcol_l = ((lane >> 3) & 1) * 8;
    const int prow_l = ((lane >> 3) & 1) * 8 + (lane & 7);   // P A-frag rows
    const int pcol_l = (lane >> 4) * 8;
    const int lrow   = ((lane >> 3) & 1) * 8 + (lane & 7);   // V trans rows
    const int lcol   = (lane >> 4) * 8;

    for (int kt = 0; kt < nkv; ++kt) {
        CP_WAIT(0);        // kv tile kt resident
        __syncthreads();   // all warps past last iter's compute + this wait

        // prefetch next kv tile into the other stage (overwrites oldest/Q)
        if (kt + 1 < nkv) load_kv((kt + 1) & 1, kt + 1);
        CP_COMMIT();       // always commit (uniform group accounting)

        const uint32_t Kst = sb + (kt & 1) * KV_ST_B;
        const uint32_t Vst = Kst + KV_K_B;

        // ---- S = Q @ K^T : 8 k16-steps x 4 nt-pairs (ldmatrix.x4) ----
        float sfr[8][4];
#pragma unroll
        for (int nt = 0; nt < 8; ++nt)
#pragma unroll
            for (int e = 0; e < 4; ++e) sfr[nt][e] = 0.0f;

#pragma unroll
        for (int ks = 0; ks < 8; ++ks) {
#pragma unroll
            for (int ntp = 0; ntp < 4; ++ntp) {
                uint32_t bb[4];
                LDSM4(bb, Kst + ((ntp * 16 + krow_l) * KST2 + ks * 16 + kcol_l) * 2);
                mma16(sfr[2 * ntp + 0], qa[ks], &bb[0]);
                mma16(sfr[2 * ntp + 1], qa[ks], &bb[2]);
            }
        }

        // scale + causal mask (kv cols kt*64.. vs Q rows qt*128..):
        // mask applies when kt >= 2*qt; col offset within Q tile = (kt-2qt)*64
#pragma unroll
        for (int nt = 0; nt < 8; ++nt) {
#pragma unroll
            for (int e = 0; e < 4; ++e) sfr[nt][e] *= sc;
            if (kt >= 2 * qt) {
                int col = (kt - 2 * qt) * 64 + nt * 8 + 2 * kq;
                if (col + 0 > rowlo) sfr[nt][0] = -1e9f;
                if (col + 1 > rowlo) sfr[nt][1] = -1e9f;
                if (col + 0 > rowhi) sfr[nt][2] = -1e9f;
                if (col + 1 > rowhi) sfr[nt][3] = -1e9f;
            }
        }

        // ---- online softmax ----
        float mx0 = -1e30f, mx1 = -1e30f;
#pragma unroll
        for (int nt = 0; nt < 8; ++nt) {
            mx0 = fmaxf(mx0, fmaxf(sfr[nt][0], sfr[nt][1]));
            mx1 = fmaxf(mx1, fmaxf(sfr[nt][2], sfr[nt][3]));
        }
        mx0 = fmaxf(mx0, __shfl_xor_sync(0xffffffffu, mx0, 1));
        mx0 = fmaxf(mx0, __shfl_xor_sync(0xffffffffu, mx0, 2));
        mx1 = fmaxf(mx1, __shfl_xor_sync(0xffffffffu, mx1, 1));
        mx1 = fmaxf(mx1, __shfl_xor_sync(0xffffffffu, mx1, 2));

        float mn0 = fmaxf(m0, mx0), mn1 = fmaxf(m1, mx1);
        float c0 = __expf(m0 - mn0), c1 = __expf(m1 - mn1);
        m0 = mn0; m1 = mn1;

        float s0 = 0.0f, s1 = 0.0f;
#pragma unroll
        for (int nt = 0; nt < 8; ++nt) {
            sfr[nt][0] = __expf(sfr[nt][0] - m0);
            sfr[nt][1] = __expf(sfr[nt][1] - m0);
            sfr[nt][2] = __expf(sfr[nt][2] - m1);
            sfr[nt][3] = __expf(sfr[nt][3] - m1);
            s0 += sfr[nt][0] + sfr[nt][1];
            s1 += sfr[nt][2] + sfr[nt][3];
        }
        s0 += __shfl_xor_sync(0xffffffffu, s0, 1);
        s0 += __shfl_xor_sync(0xffffffffu, s0, 2);
        s1 += __shfl_xor_sync(0xffffffffu, s1, 1);
        s1 += __shfl_xor_sync(0xffffffffu, s1, 2);
        l0 = l0 * c0 + s0;
        l1 = l1 * c1 + s1;

#pragma unroll
        for (int nt = 0; nt < 16; ++nt) {
            o[nt][0] *= c0; o[nt][1] *= c0;
            o[nt][2] *= c1; o[nt][3] *= c1;
        }

        // ---- P (fp16) to warp-private smem ----
        __half* Pw = Ps + w * (16 * PST2);
        const uint32_t Pwb = smem_addr(Pw);
#pragma unroll
        for (int nt = 0; nt < 8; ++nt) {
            int col = nt * 8 + 2 * kq;
            *reinterpret_cast<uint32_t*>(Pw + grp * PST2 + col) =
                pack2(sfr[nt][0], sfr[nt][1]);
            *reinterpret_cast<uint32_t*>(Pw + (grp + 8) * PST2 + col) =
                pack2(sfr[nt][2], sfr[nt][3]);
        }
        __syncwarp();

        // ---- O += P @ V : 4 k16-steps; P via ldmatrix, V via ldmatrix.trans ----
#pragma unroll
        for (int ks = 0; ks < 4; ++ks) {
            uint32_t a[4];
            LDSM4(a, Pwb + (prow_l * PST2 + ks * 16 + pcol_l) * 2);
            const uint32_t vbase = Vst + ((ks * 16 + lrow) * VST2 + lcol) * 2;
#pragma unroll
            for (int ntp = 0; ntp < 8; ++ntp) {
                uint32_t bb[4];
                LDSM4T(bb, vbase + ntp * 32);
                mma16(o[2 * ntp + 0], a, &bb[0]);
                mma16(o[2 * ntp + 1], a, &bb[2]);
            }
        }
        __syncwarp();
    }

    // ---- epilogue: normalize, write fp32 [B,S,D] ----
    const int b = bh >> 3, h = bh & 7;
    float i0 = 1.0f / l0, i1 = 1.0f / l1;
    int q0 = qt * 128 + rowlo;
    float* r0 = O + ((size_t)b * S_LEN + q0) * DM + h * DKH;
    float* r1 = O + ((size_t)b * S_LEN + q0 + 8) * DM + h * DKH;
#pragma unroll
    for (int nt = 0; nt < 16; ++nt) {
        int col = nt * 8 + 2 * kq;
        *reinterpret_cast<float2*>(r0 + col) = make_float2(o[nt][0] * i0, o[nt][1] * i0);
        *reinterpret_cast<float2*>(r1 + col) = make_float2(o[nt][2] * i1, o[nt][3] * i1);
    }
}

// ---------------------------------------------------------------------------
// Residual + LayerNorm
// ---------------------------------------------------------------------------
__global__ __launch_bounds__(256)
void ln_kernel(const float* __restrict__ Oin, const float* __restrict__ X,
               const float* __restrict__ gamma, const float* __restrict__ beta,
               float* __restrict__ out)
{
    const int r = blockIdx.x;
    const int t = threadIdx.x;

    float4 o = reinterpret_cast<const float4*>(Oin + (size_t)r * DM)[t];
    float4 x = reinterpret_cast<const float4*>(X + (size_t)r * DM)[t];
    float v0 = o.x + x.x, v1 = o.y + x.y, v2 = o.z + x.z, v3 = o.w + x.w;

    float s1 = v0 + v1 + v2 + v3;
    float s2 = v0 * v0 + v1 * v1 + v2 * v2 + v3 * v3;
#pragma unroll
    for (int off = 16; off > 0; off >>= 1) {
        s1 += __shfl_xor_sync(0xffffffffu, s1, off);
        s2 += __shfl_xor_sync(0xffffffffu, s2, off);
    }

    __shared__ float rs1[8], rs2[8], stats[2];
    int warp = t >> 5, lane = t & 31;
    if (lane == 0) { rs1[warp] = s1; rs2[warp] = s2; }
    __syncthreads();
    if (t == 0) {
        float a = 0.0f, b2 = 0.0f;
#pragma unroll
        for (int wdx = 0; wdx < 8; ++wdx) { a += rs1[wdx]; b2 += rs2[wdx]; }
        float mean = a * (1.0f / 1024.0f);
        float var  = b2 * (1.0f / 1024.0f) - mean * mean;
        stats[0] = mean;
        stats[1] = rsqrtf(var + 1e-6f);
    }
    __syncthreads();
    float mean = stats[0], rstd = stats[1];

    float4 g  = reinterpret_cast<const float4*>(gamma)[t];
    float4 bb = reinterpret_cast<const float4*>(beta)[t];
    float4 y;
    y.x = (v0 - mean) * rstd * g.x + bb.x;
    y.y = (v1 - mean) * rstd * g.y + bb.y;
    y.z = (v2 - mean) * rstd * g.z + bb.z;
    y.w = (v3 - mean) * rstd * g.w + bb.w;
    reinterpret_cast<float4*>(out + (size_t)r * DM)[t] = y;
}

// ---------------------------------------------------------------------------
// Launcher
// ---------------------------------------------------------------------------
extern "C" void kernel_launch(void* const* d_in, const int* in_sizes, int n_in,
                              void* d_out, int out_size)
{
    const float* q     = (const float*)d_in[0];
    const float* k     = (const float*)d_in[1];
    const float* v     = (const float*)d_in[2];
    const float* Wq    = (const float*)d_in[3];
    const float* bq    = (const float*)d_in[4];
    const float* Wk    = (const float*)d_in[5];
    const float* bk    = (const float*)d_in[6];
    const float* Wv    = (const float*)d_in[7];
    const float* bv    = (const float*)d_in[8];
    const float* gamma = (const float*)d_in[9];
    const float* beta  = (const float*)d_in[10];
    float* out = (float*)d_out;

    __half *Qp, *Kp, *Vp, *WqT, *WkT, *WvT, *qh, *kh, *vh;
    float *Op;
    cudaGetSymbolAddress((void**)&Qp, g_Q);
    cudaGetSymbolAddress((void**)&Kp, g_K);
    cudaGetSymbolAddress((void**)&Vp, g_V);
    cudaGetSymbolAddress((void**)&Op, g_O);
    cudaGetSymbolAddress((void**)&WqT, g_WqT);
    cudaGetSymbolAddress((void**)&WkT, g_WkT);
    cudaGetSymbolAddress((void**)&WvT, g_WvT);
    cudaGetSymbolAddress((void**)&qh, g_qh);
    cudaGetSymbolAddress((void**)&kh, g_kh);
    cudaGetSymbolAddress((void**)&vh, g_vh);

    cudaFuncSetAttribute(gemm_h3, cudaFuncAttributeMaxDynamicSharedMemorySize,
                         GEMM_SMEM);
    cudaFuncSetAttribute(attn_h, cudaFuncAttributeMaxDynamicSharedMemorySize,
                         ATT_SMEM);

    // fp32 -> fp16 input copies (launches 0-2)
    f2h<<<8192, 256>>>((const float4*)q, (uint2*)qh);
    f2h<<<8192, 256>>>((const float4*)k, (uint2*)kh);
    f2h<<<8192, 256>>>((const float4*)v, (uint2*)vh);

    // W[k][n] -> W^T[n][k] (fp16), all 3 in one launch (launch 3)
    transpose_h3<<<dim3(32, 32, 3), dim3(32, 8)>>>(Wq, Wk, Wv, WqT, WkT, WvT);

    // QKV projections fused into one launch (launch 4)
    gemm_h3<<<dim3(8, 64, 3), 256, GEMM_SMEM>>>(qh, kh, vh, WqT, WkT, WvT,
                                                bq, bk, bv, Qp, Kp, Vp);

    // attention (launch 5 — lands in the ncu profile slot)
    attn_h<<<dim3(16, 32), 256, ATT_SMEM>>>(Qp, Kp, Vp, Op);

    ln_kernel<<<8192, 256>>>(Op, q, gamma, beta, out);
}